// round 1
// baseline (speedup 1.0000x reference)
#include <cuda_runtime.h>
#include <math.h>

// Problem constants
#define Bc  2
#define Sc  2048
#define Ec  2048
#define Ac  2048
#define Hc  16
#define HDc 128

// Scratch (device globals — no allocations allowed)
__device__ float g_Q[Bc*Hc*Sc*HDc];      // 32MB
__device__ float g_K[Bc*Hc*Sc*HDc];      // 32MB
__device__ float g_V[Bc*Hc*Sc*HDc];      // 32MB
__device__ float g_attn[Bc*Sc*Ac];       // 32MB
__device__ float g_cos[Sc*(HDc/2)];
__device__ float g_sin[Sc*(HDc/2)];

// ---------------------------------------------------------------------------
// RoPE table (double precision internally; reference computes fp32 — error
// bounded by fp32 angle rounding ~1e-4 worst case, well under 1e-3).
// ---------------------------------------------------------------------------
__global__ void rope_table_kernel() {
    int idx = blockIdx.x * blockDim.x + threadIdx.x;
    if (idx >= Sc * (HDc/2)) return;
    int pos = idx / (HDc/2);
    int j   = idx % (HDc/2);
    double inv = pow(10000.0, -((double)(2*j)) / (double)HDc);
    double a = (double)pos * inv;
    g_cos[idx] = (float)cos(a);
    g_sin[idx] = (float)sin(a);
}

// ---------------------------------------------------------------------------
// 128x128x8 tiled SGEMM, 256 threads, 8x8 per-thread micro-tile.
// mode 0: C = A@B written row-major to C [M,N]
// mode 1: QKV epilogue — scatter to g_Q/g_K/g_V in [B,H,S,HD] layout with
//         RoPE applied to Q and K. (A=x, B=W_qkv, C unused)
// If A==nullptr, use g_attn as the A operand (device-global scratch).
// ---------------------------------------------------------------------------
__global__ __launch_bounds__(256) void sgemm128(
    const float* __restrict__ A, const float* __restrict__ Bm,
    float* __restrict__ C, int M, int N, int K, int mode)
{
    __shared__ float As[8][128];
    __shared__ float Bs[8][128];

    const float* Ap = A ? A : g_attn;

    int tid = threadIdx.x;
    int tx = tid & 15, ty = tid >> 4;
    int m0 = blockIdx.y * 128, n0 = blockIdx.x * 128;

    float acc[8][8];
    #pragma unroll
    for (int i = 0; i < 8; i++)
        #pragma unroll
        for (int j = 0; j < 8; j++) acc[i][j] = 0.f;

    int arow = tid >> 1;            // 0..127
    int ak   = (tid & 1) * 4;       // 0 or 4
    int brow = tid >> 5;            // 0..7
    int bcol = (tid & 31) * 4;      // 0..124

    const float* Aptr = Ap + (size_t)(m0 + arow) * K + ak;
    const float* Bptr = Bm + (size_t)brow * N + n0 + bcol;

    for (int k0 = 0; k0 < K; k0 += 8) {
        float4 a4 = *(const float4*)(Aptr + k0);
        float4 b4 = *(const float4*)(Bptr + (size_t)k0 * N);
        As[ak+0][arow] = a4.x; As[ak+1][arow] = a4.y;
        As[ak+2][arow] = a4.z; As[ak+3][arow] = a4.w;
        *(float4*)&Bs[brow][bcol] = b4;
        __syncthreads();
        #pragma unroll
        for (int kk = 0; kk < 8; kk++) {
            float af[8], bf[8];
            *(float4*)&af[0] = *(const float4*)&As[kk][ty*8];
            *(float4*)&af[4] = *(const float4*)&As[kk][ty*8+4];
            *(float4*)&bf[0] = *(const float4*)&Bs[kk][tx*8];
            *(float4*)&bf[4] = *(const float4*)&Bs[kk][tx*8+4];
            #pragma unroll
            for (int i = 0; i < 8; i++)
                #pragma unroll
                for (int j = 0; j < 8; j++)
                    acc[i][j] += af[i] * bf[j];
        }
        __syncthreads();
    }

    if (mode == 0) {
        #pragma unroll
        for (int i = 0; i < 8; i++) {
            float* crow = C + (size_t)(m0 + ty*8 + i) * N + n0 + tx*8;
            *(float4*)crow       = make_float4(acc[i][0], acc[i][1], acc[i][2], acc[i][3]);
            *(float4*)(crow + 4) = make_float4(acc[i][4], acc[i][5], acc[i][6], acc[i][7]);
        }
    } else {
        // QKV scatter + RoPE.  n = t*A + h*HD + d  (t in {0:Q,1:K,2:V})
        int nbase = n0 + tx*8;
        int t     = nbase / Ac;
        int rem   = nbase % Ac;
        int h     = rem / HDc;
        int dbase = rem % HDc;            // multiple of 8, pairs stay in-thread
        float* dst = (t == 0) ? g_Q : (t == 1) ? g_K : g_V;
        #pragma unroll
        for (int i = 0; i < 8; i++) {
            int m = m0 + ty*8 + i;
            int b = m / Sc, s = m % Sc;
            float* row = dst + (((size_t)(b*Hc + h) * Sc + s) * HDc + dbase);
            if (t == 2) {
                #pragma unroll
                for (int j = 0; j < 8; j++) row[j] = acc[i][j];
            } else {
                #pragma unroll
                for (int j = 0; j < 8; j += 2) {
                    int jj = (dbase + j) >> 1;
                    float c  = g_cos[s*(HDc/2) + jj];
                    float sn = g_sin[s*(HDc/2) + jj];
                    float x1 = acc[i][j], x2 = acc[i][j+1];
                    row[j]   = x1*c  - x2*sn;
                    row[j+1] = x1*sn + x2*c;
                }
            }
        }
    }
}

// ---------------------------------------------------------------------------
// Flash attention, fp32.  BM=128 q-rows, BN=64 k-cols per iter, 512 threads.
// Thread (tx in [0,16), ty in [0,32)) owns score tile rows ty*4+i (4 rows)
// x cols tx*4+j; O accumulator rows ty*4+i x dims tx*8..+7.
// Row reductions via shfl within 16-lane half-warps.
// Writes result directly in [b, s, h*HD+d] layout to g_attn.
// ---------------------------------------------------------------------------
__global__ __launch_bounds__(512) void flash_attn_kernel() {
    extern __shared__ float sm[];
    float* Qs  = sm;                 // [128][128]
    float* Kst = sm + 16384;         // [128][64]  (transposed: [d][col])
    float* Vs  = sm + 24576;         // [64][128]
    float* Ps  = sm + 32768;         // [128][64]

    int tid = threadIdx.x;
    int tx = tid & 15, ty = tid >> 4;
    int qb = blockIdx.x;             // q-tile (0..15)
    int bh = blockIdx.y;             // b*H + h (0..31)

    const float* Qg = g_Q + ((size_t)bh * Sc + qb*128) * HDc;
    const float* Kg = g_K + (size_t)bh * Sc * HDc;
    const float* Vg = g_V + (size_t)bh * Sc * HDc;

    // Load Q tile (layout matches global: [row][d])
    for (int i = tid; i < 128*128/4; i += 512) {
        int lin = i * 4;
        *(float4*)&Qs[lin] = *(const float4*)&Qg[lin];
    }

    float m_i[4], l_i[4], acc[4][8];
    #pragma unroll
    for (int i = 0; i < 4; i++) {
        m_i[i] = -INFINITY; l_i[i] = 0.f;
        #pragma unroll
        for (int k = 0; k < 8; k++) acc[i][k] = 0.f;
    }

    const float scale = 0.08838834764831845f;  // 1/sqrt(128)

    __syncthreads();

    for (int kt = 0; kt < Sc/64; kt++) {
        // Load K (transposed into [d][col]) and V ([col][d])
        for (int i = tid; i < 64*128/4; i += 512) {
            int lin = i * 4;
            int row = lin >> 7;
            int d   = lin & 127;
            float4 k4 = *(const float4*)&Kg[(size_t)kt*64*128 + lin];
            Kst[(d+0)*64 + row] = k4.x;
            Kst[(d+1)*64 + row] = k4.y;
            Kst[(d+2)*64 + row] = k4.z;
            Kst[(d+3)*64 + row] = k4.w;
            *(float4*)&Vs[lin] = *(const float4*)&Vg[(size_t)kt*64*128 + lin];
        }
        __syncthreads();

        // Scores s[4][4]
        float s[4][4];
        #pragma unroll
        for (int i = 0; i < 4; i++)
            #pragma unroll
            for (int j = 0; j < 4; j++) s[i][j] = 0.f;

        for (int d = 0; d < 128; d += 4) {
            float4 qa[4], ka[4];
            #pragma unroll
            for (int i = 0; i < 4; i++)
                qa[i] = *(const float4*)&Qs[(ty*4 + i)*128 + d];
            #pragma unroll
            for (int dd = 0; dd < 4; dd++)
                ka[dd] = *(const float4*)&Kst[(d + dd)*64 + tx*4];
            #pragma unroll
            for (int i = 0; i < 4; i++) {
                const float* qp = (const float*)&qa[i];
                #pragma unroll
                for (int dd = 0; dd < 4; dd++) {
                    const float* kp = (const float*)&ka[dd];
                    float qv = qp[dd];
                    s[i][0] += qv * kp[0];
                    s[i][1] += qv * kp[1];
                    s[i][2] += qv * kp[2];
                    s[i][3] += qv * kp[3];
                }
            }
        }

        // Online softmax (row reductions over the 16 tx lanes)
        #pragma unroll
        for (int i = 0; i < 4; i++) {
            #pragma unroll
            for (int j = 0; j < 4; j++) s[i][j] *= scale;
            float mloc = fmaxf(fmaxf(s[i][0], s[i][1]), fmaxf(s[i][2], s[i][3]));
            #pragma unroll
            for (int off = 1; off < 16; off <<= 1)
                mloc = fmaxf(mloc, __shfl_xor_sync(0xffffffffu, mloc, off));
            float m_new = fmaxf(m_i[i], mloc);
            float p0 = __expf(s[i][0] - m_new);
            float p1 = __expf(s[i][1] - m_new);
            float p2 = __expf(s[i][2] - m_new);
            float p3 = __expf(s[i][3] - m_new);
            float lloc = p0 + p1 + p2 + p3;
            #pragma unroll
            for (int off = 1; off < 16; off <<= 1)
                lloc += __shfl_xor_sync(0xffffffffu, lloc, off);
            float corr = __expf(m_i[i] - m_new);
            l_i[i] = l_i[i] * corr + lloc;
            m_i[i] = m_new;
            #pragma unroll
            for (int k = 0; k < 8; k++) acc[i][k] *= corr;
            float* prow = &Ps[(ty*4 + i)*64 + tx*4];
            prow[0] = p0; prow[1] = p1; prow[2] = p2; prow[3] = p3;
        }
        __syncthreads();

        // O += P @ V
        for (int c = 0; c < 64; c++) {
            float4 v0 = *(const float4*)&Vs[c*128 + tx*8];
            float4 v1 = *(const float4*)&Vs[c*128 + tx*8 + 4];
            #pragma unroll
            for (int i = 0; i < 4; i++) {
                float p = Ps[(ty*4 + i)*64 + c];
                acc[i][0] += p * v0.x; acc[i][1] += p * v0.y;
                acc[i][2] += p * v0.z; acc[i][3] += p * v0.w;
                acc[i][4] += p * v1.x; acc[i][5] += p * v1.y;
                acc[i][6] += p * v1.z; acc[i][7] += p * v1.w;
            }
        }
        __syncthreads();
    }

    // Epilogue: normalize and write [b, s, h*HD + d]
    int b = bh / Hc, h = bh % Hc;
    #pragma unroll
    for (int i = 0; i < 4; i++) {
        int q = qb*128 + ty*4 + i;
        float inv = 1.f / l_i[i];
        float* dstp = g_attn + ((size_t)(b*Sc + q) * Ac + h*HDc + tx*8);
        *(float4*)dstp =
            make_float4(acc[i][0]*inv, acc[i][1]*inv, acc[i][2]*inv, acc[i][3]*inv);
        *(float4*)(dstp + 4) =
            make_float4(acc[i][4]*inv, acc[i][5]*inv, acc[i][6]*inv, acc[i][7]*inv);
    }
}

// ---------------------------------------------------------------------------
extern "C" void kernel_launch(void* const* d_in, const int* in_sizes, int n_in,
                              void* d_out, int out_size) {
    // Identify inputs by element count (robust to ordering)
    const float *x = nullptr, *wqkv = nullptr, *wout = nullptr;
    for (int i = 0; i < n_in; i++) {
        int sz = in_sizes[i];
        if (sz == Bc*Sc*Ec)            x    = (const float*)d_in[i];   // 8388608
        else if (sz == Ec*3*Ac)        wqkv = (const float*)d_in[i];   // 12582912
        else if (sz == Ac*Ec)          wout = (const float*)d_in[i];   // 4194304
    }
    float* out = (float*)d_out;

    const int M = Bc * Sc;  // 4096

    // 1. RoPE tables
    rope_table_kernel<<<(Sc*(HDc/2) + 255)/256, 256>>>();

    // 2. QKV GEMM + RoPE + scatter   [4096,2048] @ [2048,6144]
    sgemm128<<<dim3(3*Ac/128, M/128), 256>>>(x, wqkv, nullptr, M, 3*Ac, Ec, 1);

    // 3. Flash attention -> g_attn [b, s, A]
    cudaFuncSetAttribute(flash_attn_kernel,
                         cudaFuncAttributeMaxDynamicSharedMemorySize, 163840);
    flash_attn_kernel<<<dim3(Sc/128, Bc*Hc), 512, 163840>>>();

    // 4. Output projection   [4096,2048] @ [2048,2048] -> d_out
    sgemm128<<<dim3(Ec/128, M/128), 256>>>(nullptr, wout, out, M, Ec, Ac, 0);
}

// round 2
// speedup vs baseline: 2.6741x; 2.6741x over previous
#include <cuda_runtime.h>
#include <math.h>

#define Bc  2
#define Sc  2048
#define Ec  2048
#define Ac  2048
#define Hc  16
#define HDc 128

// Scratch (device globals — no allocations allowed)
__device__ float g_Q[Bc*Hc*Sc*HDc];
__device__ float g_K[Bc*Hc*Sc*HDc];
__device__ float g_V[Bc*Hc*Sc*HDc];
__device__ float g_attn[Bc*Sc*Ac];
__device__ float g_cos[Sc*(HDc/2)];
__device__ float g_sin[Sc*(HDc/2)];

// ---------------------------------------------------------------------------
__device__ __forceinline__ unsigned f2tf(float f) {
    unsigned u; asm("cvt.rna.tf32.f32 %0, %1;" : "=r"(u) : "f"(f)); return u;
}
__device__ __forceinline__ void mma_tf32(float* c, const unsigned* a, const unsigned* b) {
    asm volatile("mma.sync.aligned.m16n8k8.row.col.f32.tf32.tf32.f32 "
        "{%0,%1,%2,%3}, {%4,%5,%6,%7}, {%8,%9}, {%0,%1,%2,%3};"
        : "+f"(c[0]), "+f"(c[1]), "+f"(c[2]), "+f"(c[3])
        : "r"(a[0]), "r"(a[1]), "r"(a[2]), "r"(a[3]), "r"(b[0]), "r"(b[1]));
}

// ---------------------------------------------------------------------------
__global__ void rope_table_kernel() {
    int idx = blockIdx.x * blockDim.x + threadIdx.x;
    if (idx >= Sc * (HDc/2)) return;
    int pos = idx / (HDc/2);
    int j   = idx % (HDc/2);
    double inv = pow(10000.0, -((double)(2*j)) / (double)HDc);
    double a = (double)pos * inv;
    g_cos[idx] = (float)cos(a);
    g_sin[idx] = (float)sin(a);
}

// ---------------------------------------------------------------------------
// Tensor-core tf32 GEMM, 128x128 block tile, BK=16, 8 warps (2x4 warp grid,
// warp tile 64x32). mode 0: C = A@B. mode 1: QKV epilogue with RoPE scatter.
// A==nullptr -> use g_attn as A.
// ---------------------------------------------------------------------------
#define BK 16
__global__ __launch_bounds__(256, 1) void gemm_tc(
    const float* __restrict__ A, const float* __restrict__ Bm,
    float* __restrict__ C, int M, int N, int K, int mode)
{
    __shared__ unsigned As[128*20];   // [m][k], stride 20 (conflict-free frag loads)
    __shared__ unsigned Bs[BK*136];   // [k][n], stride 136

    const float* Ap = A ? A : g_attn;

    int tid  = threadIdx.x;
    int warp = tid >> 5, lane = tid & 31;
    int g = lane >> 2, t4 = lane & 3;
    int wm = warp >> 2, wn = warp & 3;
    int m0 = blockIdx.y * 128, n0 = blockIdx.x * 128;

    float acc[4][4][4];
    #pragma unroll
    for (int i = 0; i < 4; i++)
        #pragma unroll
        for (int j = 0; j < 4; j++)
            #pragma unroll
            for (int r = 0; r < 4; r++) acc[i][j][r] = 0.f;

    int arow = tid >> 2, aq = (tid & 3) * 4;   // A: 128 rows x 16k
    int brow = tid >> 5, bnc = (tid & 31) * 4; // B: 16 rows x 128n

    for (int k0 = 0; k0 < K; k0 += BK) {
        #pragma unroll
        for (int h = 0; h < 2; h++) {
            int row = arow + h*64;
            float4 v = *(const float4*)(Ap + (size_t)(m0+row)*K + k0 + aq);
            *(uint4*)&As[row*20 + aq] =
                make_uint4(f2tf(v.x), f2tf(v.y), f2tf(v.z), f2tf(v.w));
        }
        #pragma unroll
        for (int h = 0; h < 2; h++) {
            int kr = brow + h*8;
            float4 v = *(const float4*)(Bm + (size_t)(k0+kr)*N + n0 + bnc);
            *(uint4*)&Bs[kr*136 + bnc] =
                make_uint4(f2tf(v.x), f2tf(v.y), f2tf(v.z), f2tf(v.w));
        }
        __syncthreads();

        #pragma unroll
        for (int kk = 0; kk < BK; kk += 8) {
            unsigned a[4][4], b[4][2];
            #pragma unroll
            for (int mf = 0; mf < 4; mf++) {
                int r = wm*64 + mf*16 + g;
                a[mf][0] = As[r*20 + kk + t4];
                a[mf][1] = As[(r+8)*20 + kk + t4];
                a[mf][2] = As[r*20 + kk + t4 + 4];
                a[mf][3] = As[(r+8)*20 + kk + t4 + 4];
            }
            #pragma unroll
            for (int nf = 0; nf < 4; nf++) {
                int c = wn*32 + nf*8 + g;
                b[nf][0] = Bs[(kk+t4)*136 + c];
                b[nf][1] = Bs[(kk+t4+4)*136 + c];
            }
            #pragma unroll
            for (int mf = 0; mf < 4; mf++)
                #pragma unroll
                for (int nf = 0; nf < 4; nf++)
                    mma_tf32(acc[mf][nf], a[mf], b[nf]);
        }
        __syncthreads();
    }

    if (mode == 0) {
        #pragma unroll
        for (int mf = 0; mf < 4; mf++)
            #pragma unroll
            for (int nf = 0; nf < 4; nf++) {
                int row = m0 + wm*64 + mf*16 + g;
                int col = n0 + wn*32 + nf*8 + 2*t4;
                *(float2*)(C + (size_t)row*N + col) =
                    make_float2(acc[mf][nf][0], acc[mf][nf][1]);
                *(float2*)(C + (size_t)(row+8)*N + col) =
                    make_float2(acc[mf][nf][2], acc[mf][nf][3]);
            }
    } else {
        #pragma unroll
        for (int nf = 0; nf < 4; nf++) {
            int n   = n0 + wn*32 + nf*8 + 2*t4;
            int t   = n / Ac;
            int rem = n % Ac;
            int h   = rem >> 7;
            int d   = rem & 127;
            int j   = d >> 1;
            float* dst = (t == 0) ? g_Q : (t == 1) ? g_K : g_V;
            #pragma unroll
            for (int mf = 0; mf < 4; mf++) {
                #pragma unroll
                for (int half = 0; half < 2; half++) {
                    int row = m0 + wm*64 + mf*16 + g + half*8;
                    int b = row >> 11, s = row & 2047;
                    float c0 = acc[mf][nf][half*2];
                    float c1 = acc[mf][nf][half*2 + 1];
                    float* p = dst + (((size_t)(b*Hc + h)*Sc + s) << 7) + d;
                    if (t == 2) { p[0] = c0; p[1] = c1; }
                    else {
                        float cs = g_cos[s*64 + j], sn = g_sin[s*64 + j];
                        p[0] = c0*cs - c1*sn;
                        p[1] = c0*sn + c1*cs;
                    }
                }
            }
        }
    }
}

// ---------------------------------------------------------------------------
// Tensor-core flash attention. BM=128 q-rows, BN=64 kv-cols/iter, 256 threads.
// Warp w owns q-rows w*16..w*16+15 and all 64 cols + all 128 out dims.
// ---------------------------------------------------------------------------
__global__ __launch_bounds__(256, 1) void flash_tc() {
    extern __shared__ unsigned sm[];
    unsigned* Qs = sm;                 // [128][132] tf32 bits
    unsigned* Ks = Qs + 128*132;       // [64][132]
    unsigned* Vs = Ks + 64*132;        // [64][136]
    unsigned* Ps = Vs + 64*136;        // 8 warps x [16][68]

    int tid  = threadIdx.x;
    int warp = tid >> 5, lane = tid & 31;
    int g = lane >> 2, t4 = lane & 3;
    int qb = blockIdx.x, bh = blockIdx.y;

    const float* Qg = g_Q + (((size_t)bh*Sc + qb*128) << 7);
    const float* Kg = g_K + ((size_t)bh*Sc << 7);
    const float* Vg = g_V + ((size_t)bh*Sc << 7);

    // Stage Q tile (tf32 bits)
    #pragma unroll
    for (int i = 0; i < 16; i++) {
        int f = tid + i*256;
        int row = f >> 5, c = (f & 31) * 4;
        float4 v = *(const float4*)(Qg + row*128 + c);
        *(uint4*)&Qs[row*132 + c] =
            make_uint4(f2tf(v.x), f2tf(v.y), f2tf(v.z), f2tf(v.w));
    }

    float m_i[2] = {-INFINITY, -INFINITY}, l_i[2] = {0.f, 0.f};
    float o[16][4];
    #pragma unroll
    for (int nf = 0; nf < 16; nf++)
        #pragma unroll
        for (int r = 0; r < 4; r++) o[nf][r] = 0.f;

    const float scale = 0.08838834764831845f;
    int rbase = warp * 16;
    unsigned* Pw = Ps + warp * 16 * 68;

    __syncthreads();

    for (int kt = 0; kt < Sc/64; kt++) {
        // Load K and V tiles (64x128)
        #pragma unroll
        for (int i = 0; i < 8; i++) {
            int f = tid + i*256;
            int row = f >> 5, c = (f & 31) * 4;
            float4 k4 = *(const float4*)(Kg + (size_t)kt*8192 + row*128 + c);
            float4 v4 = *(const float4*)(Vg + (size_t)kt*8192 + row*128 + c);
            *(uint4*)&Ks[row*132 + c] =
                make_uint4(f2tf(k4.x), f2tf(k4.y), f2tf(k4.z), f2tf(k4.w));
            *(uint4*)&Vs[row*136 + c] =
                make_uint4(f2tf(v4.x), f2tf(v4.y), f2tf(v4.z), f2tf(v4.w));
        }
        __syncthreads();

        // S = Q @ K^T  (K read un-transposed as col-major B operand)
        float s[8][4];
        #pragma unroll
        for (int nf = 0; nf < 8; nf++)
            #pragma unroll
            for (int r = 0; r < 4; r++) s[nf][r] = 0.f;

        #pragma unroll 4
        for (int ks = 0; ks < 16; ks++) {
            unsigned a[4];
            a[0] = Qs[(rbase+g)*132   + ks*8 + t4];
            a[1] = Qs[(rbase+g+8)*132 + ks*8 + t4];
            a[2] = Qs[(rbase+g)*132   + ks*8 + t4 + 4];
            a[3] = Qs[(rbase+g+8)*132 + ks*8 + t4 + 4];
            #pragma unroll
            for (int nf = 0; nf < 8; nf++) {
                unsigned b[2];
                b[0] = Ks[(nf*8+g)*132 + ks*8 + t4];
                b[1] = Ks[(nf*8+g)*132 + ks*8 + t4 + 4];
                mma_tf32(s[nf], a, b);
            }
        }

        // Online softmax (rows r0 = rbase+g, r1 = r0+8)
        #pragma unroll
        for (int half = 0; half < 2; half++) {
            float mx = -INFINITY;
            #pragma unroll
            for (int nf = 0; nf < 8; nf++) {
                mx = fmaxf(mx, fmaxf(s[nf][half*2], s[nf][half*2+1]));
            }
            mx *= scale;
            mx = fmaxf(mx, __shfl_xor_sync(0xffffffffu, mx, 1));
            mx = fmaxf(mx, __shfl_xor_sync(0xffffffffu, mx, 2));
            float m_new = fmaxf(m_i[half], mx);
            float corr  = __expf(m_i[half] - m_new);
            float lsum  = 0.f;
            #pragma unroll
            for (int nf = 0; nf < 8; nf++) {
                float p0 = __expf(s[nf][half*2]   * scale - m_new);
                float p1 = __expf(s[nf][half*2+1] * scale - m_new);
                s[nf][half*2]   = p0;
                s[nf][half*2+1] = p1;
                lsum += p0 + p1;
            }
            lsum += __shfl_xor_sync(0xffffffffu, lsum, 1);
            lsum += __shfl_xor_sync(0xffffffffu, lsum, 2);
            l_i[half] = l_i[half] * corr + lsum;
            m_i[half] = m_new;
            #pragma unroll
            for (int nf = 0; nf < 16; nf++) {
                o[nf][half*2]   *= corr;
                o[nf][half*2+1] *= corr;
            }
        }

        // Store P (tf32 bits) to per-warp slab
        #pragma unroll
        for (int nf = 0; nf < 8; nf++) {
            int col = nf*8 + 2*t4;
            Pw[g*68 + col]     = f2tf(s[nf][0]);
            Pw[g*68 + col + 1] = f2tf(s[nf][1]);
            Pw[(g+8)*68 + col]     = f2tf(s[nf][2]);
            Pw[(g+8)*68 + col + 1] = f2tf(s[nf][3]);
        }
        __syncwarp();

        // O += P @ V
        #pragma unroll 2
        for (int ks = 0; ks < 8; ks++) {
            unsigned a[4];
            a[0] = Pw[g*68     + ks*8 + t4];
            a[1] = Pw[(g+8)*68 + ks*8 + t4];
            a[2] = Pw[g*68     + ks*8 + t4 + 4];
            a[3] = Pw[(g+8)*68 + ks*8 + t4 + 4];
            #pragma unroll
            for (int nf = 0; nf < 16; nf++) {
                unsigned b[2];
                b[0] = Vs[(ks*8+t4)*136   + nf*8 + g];
                b[1] = Vs[(ks*8+t4+4)*136 + nf*8 + g];
                mma_tf32(o[nf], a, b);
            }
        }
        __syncthreads();
    }

    // Epilogue: normalize, write [b, s, h*HD + d]
    int b = bh / Hc, h = bh % Hc;
    float inv0 = 1.f / l_i[0], inv1 = 1.f / l_i[1];
    #pragma unroll
    for (int nf = 0; nf < 16; nf++) {
        int d = nf*8 + 2*t4;
        int r0 = qb*128 + rbase + g;
        float* p0 = g_attn + (((size_t)(b*Sc + r0)) << 11) + h*128 + d;
        *(float2*)p0 = make_float2(o[nf][0]*inv0, o[nf][1]*inv0);
        float* p1 = g_attn + (((size_t)(b*Sc + r0 + 8)) << 11) + h*128 + d;
        *(float2*)p1 = make_float2(o[nf][2]*inv1, o[nf][3]*inv1);
    }
}

// ---------------------------------------------------------------------------
extern "C" void kernel_launch(void* const* d_in, const int* in_sizes, int n_in,
                              void* d_out, int out_size) {
    const float *x = nullptr, *wqkv = nullptr, *wout = nullptr;
    for (int i = 0; i < n_in; i++) {
        int sz = in_sizes[i];
        if (sz == Bc*Sc*Ec)     x    = (const float*)d_in[i];
        else if (sz == Ec*3*Ac) wqkv = (const float*)d_in[i];
        else if (sz == Ac*Ec)   wout = (const float*)d_in[i];
    }
    float* out = (float*)d_out;
    const int M = Bc * Sc;  // 4096

    rope_table_kernel<<<(Sc*(HDc/2) + 255)/256, 256>>>();

    // QKV GEMM + RoPE + scatter
    gemm_tc<<<dim3(3*Ac/128, M/128), 256>>>(x, wqkv, nullptr, M, 3*Ac, Ec, 1);

    // Flash attention
    static int smem_set = 0;
    if (!smem_set) {
        cudaFuncSetAttribute(flash_tc,
            cudaFuncAttributeMaxDynamicSharedMemorySize, 180*1024);
        smem_set = 1;
    }
    size_t smem = (128*132 + 64*132 + 64*136 + 8*16*68) * sizeof(unsigned);
    flash_tc<<<dim3(Sc/128, Bc*Hc), 256, smem>>>();

    // Output projection
    gemm_tc<<<dim3(Ec/128, M/128), 256>>>(nullptr, wout, out, M, Ec, Ac, 0);
}

// round 3
// speedup vs baseline: 3.3237x; 1.2429x over previous
#include <cuda_runtime.h>
#include <math.h>

#define Bc  2
#define Sc  2048
#define Ec  2048
#define Ac  2048
#define Hc  16
#define HDc 128

// Scratch (device globals). Q/K/V hold tf32 BIT PATTERNS (pre-converted).
__device__ unsigned g_Q[Bc*Hc*Sc*HDc];
__device__ unsigned g_K[Bc*Hc*Sc*HDc];
__device__ unsigned g_V[Bc*Hc*Sc*HDc];
__device__ float    g_attn[Bc*Sc*Ac];
__device__ float    g_cos[Sc*(HDc/2)];
__device__ float    g_sin[Sc*(HDc/2)];

// ---------------------------------------------------------------------------
__device__ __forceinline__ unsigned f2tf(float f) {
    unsigned u; asm("cvt.rna.tf32.f32 %0, %1;" : "=r"(u) : "f"(f)); return u;
}
__device__ __forceinline__ void mma_tf32(float* c, const unsigned* a, const unsigned* b) {
    asm volatile("mma.sync.aligned.m16n8k8.row.col.f32.tf32.tf32.f32 "
        "{%0,%1,%2,%3}, {%4,%5,%6,%7}, {%8,%9}, {%0,%1,%2,%3};"
        : "+f"(c[0]), "+f"(c[1]), "+f"(c[2]), "+f"(c[3])
        : "r"(a[0]), "r"(a[1]), "r"(a[2]), "r"(a[3]), "r"(b[0]), "r"(b[1]));
}
__device__ __forceinline__ void cp16(unsigned* smem_dst, const void* gsrc) {
    unsigned d = (unsigned)__cvta_generic_to_shared(smem_dst);
    asm volatile("cp.async.cg.shared.global [%0], [%1], 16;" :: "r"(d), "l"(gsrc));
}
__device__ __forceinline__ void cp_commit() {
    asm volatile("cp.async.commit_group;");
}
__device__ __forceinline__ void cp_wait0() {
    asm volatile("cp.async.wait_group 0;");
}

// ---------------------------------------------------------------------------
__global__ void rope_table_kernel() {
    int idx = blockIdx.x * blockDim.x + threadIdx.x;
    if (idx >= Sc * (HDc/2)) return;
    int pos = idx / (HDc/2);
    int j   = idx % (HDc/2);
    double inv = pow(10000.0, -((double)(2*j)) / (double)HDc);
    double a = (double)pos * inv;
    g_cos[idx] = (float)cos(a);
    g_sin[idx] = (float)sin(a);
}

// ---------------------------------------------------------------------------
// Double-buffered tf32 tensor-core GEMM. 128x128 tile, BK=16, 8 warps.
// mode 0: C = A@B (fp32). mode 1: QKV epilogue, RoPE, store tf32 bits.
// A==nullptr -> A = g_attn.
// ---------------------------------------------------------------------------
#define BK 16
__global__ __launch_bounds__(256, 1) void gemm_tc(
    const float* __restrict__ A, const float* __restrict__ Bm,
    float* __restrict__ C, int M, int N, int K, int mode)
{
    __shared__ unsigned As[2][128*20];
    __shared__ unsigned Bs[2][BK*136];

    const float* Ap = A ? A : g_attn;

    int tid  = threadIdx.x;
    int warp = tid >> 5, lane = tid & 31;
    int g = lane >> 2, t4 = lane & 3;
    int wm = warp >> 2, wn = warp & 3;
    int m0 = blockIdx.y * 128, n0 = blockIdx.x * 128;

    float acc[4][4][4];
    #pragma unroll
    for (int i = 0; i < 4; i++)
        #pragma unroll
        for (int j = 0; j < 4; j++)
            #pragma unroll
            for (int r = 0; r < 4; r++) acc[i][j][r] = 0.f;

    int arow = tid >> 2, aq = (tid & 3) * 4;   // A: 128 rows x 16 k (2 halves)
    int brow = tid >> 5, bnc = (tid & 31) * 4; // B: 16 k x 128 n (2 halves)

    const float* Aptr = Ap + (size_t)(m0 + arow) * K + aq;
    const float* Bptr = Bm + (size_t)brow * N + n0 + bnc;

    float4 ra0, ra1, rb0, rb1;
    ra0 = *(const float4*)(Aptr);
    ra1 = *(const float4*)(Aptr + (size_t)64 * K);
    rb0 = *(const float4*)(Bptr);
    rb1 = *(const float4*)(Bptr + (size_t)8 * N);

    *(uint4*)&As[0][arow*20 + aq] =
        make_uint4(f2tf(ra0.x), f2tf(ra0.y), f2tf(ra0.z), f2tf(ra0.w));
    *(uint4*)&As[0][(arow+64)*20 + aq] =
        make_uint4(f2tf(ra1.x), f2tf(ra1.y), f2tf(ra1.z), f2tf(ra1.w));
    *(uint4*)&Bs[0][brow*136 + bnc] =
        make_uint4(f2tf(rb0.x), f2tf(rb0.y), f2tf(rb0.z), f2tf(rb0.w));
    *(uint4*)&Bs[0][(brow+8)*136 + bnc] =
        make_uint4(f2tf(rb1.x), f2tf(rb1.y), f2tf(rb1.z), f2tf(rb1.w));
    __syncthreads();

    int cur = 0;
    for (int k0 = BK; k0 <= K; k0 += BK) {
        bool more = (k0 < K);
        if (more) {
            ra0 = *(const float4*)(Aptr + k0);
            ra1 = *(const float4*)(Aptr + (size_t)64 * K + k0);
            rb0 = *(const float4*)(Bptr + (size_t)k0 * N);
            rb1 = *(const float4*)(Bptr + (size_t)(k0 + 8) * N);
        }

        const unsigned* Ac_ = As[cur];
        const unsigned* Bc_ = Bs[cur];
        #pragma unroll
        for (int kk = 0; kk < BK; kk += 8) {
            unsigned a[4][4], b[4][2];
            #pragma unroll
            for (int mf = 0; mf < 4; mf++) {
                int r = wm*64 + mf*16 + g;
                a[mf][0] = Ac_[r*20 + kk + t4];
                a[mf][1] = Ac_[(r+8)*20 + kk + t4];
                a[mf][2] = Ac_[r*20 + kk + t4 + 4];
                a[mf][3] = Ac_[(r+8)*20 + kk + t4 + 4];
            }
            #pragma unroll
            for (int nf = 0; nf < 4; nf++) {
                int c = wn*32 + nf*8 + g;
                b[nf][0] = Bc_[(kk+t4)*136 + c];
                b[nf][1] = Bc_[(kk+t4+4)*136 + c];
            }
            #pragma unroll
            for (int mf = 0; mf < 4; mf++)
                #pragma unroll
                for (int nf = 0; nf < 4; nf++)
                    mma_tf32(acc[mf][nf], a[mf], b[nf]);
        }

        if (more) {
            int nxt = cur ^ 1;
            *(uint4*)&As[nxt][arow*20 + aq] =
                make_uint4(f2tf(ra0.x), f2tf(ra0.y), f2tf(ra0.z), f2tf(ra0.w));
            *(uint4*)&As[nxt][(arow+64)*20 + aq] =
                make_uint4(f2tf(ra1.x), f2tf(ra1.y), f2tf(ra1.z), f2tf(ra1.w));
            *(uint4*)&Bs[nxt][brow*136 + bnc] =
                make_uint4(f2tf(rb0.x), f2tf(rb0.y), f2tf(rb0.z), f2tf(rb0.w));
            *(uint4*)&Bs[nxt][(brow+8)*136 + bnc] =
                make_uint4(f2tf(rb1.x), f2tf(rb1.y), f2tf(rb1.z), f2tf(rb1.w));
        }
        __syncthreads();
        cur ^= 1;
    }

    if (mode == 0) {
        #pragma unroll
        for (int mf = 0; mf < 4; mf++)
            #pragma unroll
            for (int nf = 0; nf < 4; nf++) {
                int row = m0 + wm*64 + mf*16 + g;
                int col = n0 + wn*32 + nf*8 + 2*t4;
                *(float2*)(C + (size_t)row*N + col) =
                    make_float2(acc[mf][nf][0], acc[mf][nf][1]);
                *(float2*)(C + (size_t)(row+8)*N + col) =
                    make_float2(acc[mf][nf][2], acc[mf][nf][3]);
            }
    } else {
        #pragma unroll
        for (int nf = 0; nf < 4; nf++) {
            int n   = n0 + wn*32 + nf*8 + 2*t4;
            int t   = n / Ac;
            int rem = n % Ac;
            int h   = rem >> 7;
            int d   = rem & 127;
            int j   = d >> 1;
            unsigned* dst = (t == 0) ? g_Q : (t == 1) ? g_K : g_V;
            #pragma unroll
            for (int mf = 0; mf < 4; mf++) {
                #pragma unroll
                for (int half = 0; half < 2; half++) {
                    int row = m0 + wm*64 + mf*16 + g + half*8;
                    int b = row >> 11, s = row & 2047;
                    float c0 = acc[mf][nf][half*2];
                    float c1 = acc[mf][nf][half*2 + 1];
                    unsigned* p = dst + (((size_t)(b*Hc + h)*Sc + s) << 7) + d;
                    if (t == 2) { p[0] = f2tf(c0); p[1] = f2tf(c1); }
                    else {
                        float cs = g_cos[s*64 + j], sn = g_sin[s*64 + j];
                        p[0] = f2tf(c0*cs - c1*sn);
                        p[1] = f2tf(c0*sn + c1*cs);
                    }
                }
            }
        }
    }
}

// ---------------------------------------------------------------------------
// Flash attention (tf32 mma). Q/K/V in global are tf32 bits already.
// cp.async phase pipeline: V(kt) loads overlap S-compute, K(kt+1) overlap O.
// ---------------------------------------------------------------------------
__global__ __launch_bounds__(256, 1) void flash_tc() {
    extern __shared__ unsigned sm[];
    unsigned* Qs = sm;                 // [128][132]
    unsigned* Ks = Qs + 128*132;       // [64][132]
    unsigned* Vs = Ks + 64*132;        // [64][136]
    unsigned* Ps = Vs + 64*136;        // 8 warps x [16][68]

    int tid  = threadIdx.x;
    int warp = tid >> 5, lane = tid & 31;
    int g = lane >> 2, t4 = lane & 3;
    int qb = blockIdx.x, bh = blockIdx.y;

    const unsigned* Qg = g_Q + (((size_t)bh*Sc + qb*128) << 7);
    const unsigned* Kg = g_K + ((size_t)bh*Sc << 7);
    const unsigned* Vg = g_V + ((size_t)bh*Sc << 7);

    // Stage Q (raw copy, already tf32)
    #pragma unroll
    for (int i = 0; i < 16; i++) {
        int c = tid + i*256;           // 4096 16B-chunks
        int row = c >> 5, col = (c & 31) * 4;
        *(uint4*)&Qs[row*132 + col] = *(const uint4*)&Qg[row*128 + col];
    }

    // Prefetch K(0)
    #pragma unroll
    for (int i = 0; i < 8; i++) {
        int c = tid + i*256;           // 2048 chunks
        int row = c >> 5, col = (c & 31) * 4;
        cp16(&Ks[row*132 + col], Kg + row*128 + col);
    }
    cp_commit();

    float m_i[2] = {-INFINITY, -INFINITY}, l_i[2] = {0.f, 0.f};
    float o[16][4];
    #pragma unroll
    for (int nf = 0; nf < 16; nf++)
        #pragma unroll
        for (int r = 0; r < 4; r++) o[nf][r] = 0.f;

    const float scale = 0.08838834764831845f;
    int rbase = warp * 16;
    unsigned* Pw = Ps + warp * 16 * 68;

    cp_wait0();
    __syncthreads();

    for (int kt = 0; kt < Sc/64; kt++) {
        // Prefetch V(kt) under S-compute
        #pragma unroll
        for (int i = 0; i < 8; i++) {
            int c = tid + i*256;
            int row = c >> 5, col = (c & 31) * 4;
            cp16(&Vs[row*136 + col], Vg + (size_t)kt*8192 + row*128 + col);
        }
        cp_commit();

        // S = Q @ K^T
        float s[8][4];
        #pragma unroll
        for (int nf = 0; nf < 8; nf++)
            #pragma unroll
            for (int r = 0; r < 4; r++) s[nf][r] = 0.f;

        #pragma unroll 4
        for (int ks = 0; ks < 16; ks++) {
            unsigned a[4];
            a[0] = Qs[(rbase+g)*132   + ks*8 + t4];
            a[1] = Qs[(rbase+g+8)*132 + ks*8 + t4];
            a[2] = Qs[(rbase+g)*132   + ks*8 + t4 + 4];
            a[3] = Qs[(rbase+g+8)*132 + ks*8 + t4 + 4];
            #pragma unroll
            for (int nf = 0; nf < 8; nf++) {
                unsigned b[2];
                b[0] = Ks[(nf*8+g)*132 + ks*8 + t4];
                b[1] = Ks[(nf*8+g)*132 + ks*8 + t4 + 4];
                mma_tf32(s[nf], a, b);
            }
        }

        // Online softmax
        #pragma unroll
        for (int half = 0; half < 2; half++) {
            float mx = -INFINITY;
            #pragma unroll
            for (int nf = 0; nf < 8; nf++)
                mx = fmaxf(mx, fmaxf(s[nf][half*2], s[nf][half*2+1]));
            mx *= scale;
            mx = fmaxf(mx, __shfl_xor_sync(0xffffffffu, mx, 1));
            mx = fmaxf(mx, __shfl_xor_sync(0xffffffffu, mx, 2));
            float m_new = fmaxf(m_i[half], mx);
            float corr  = __expf(m_i[half] - m_new);
            float lsum  = 0.f;
            #pragma unroll
            for (int nf = 0; nf < 8; nf++) {
                float p0 = __expf(s[nf][half*2]   * scale - m_new);
                float p1 = __expf(s[nf][half*2+1] * scale - m_new);
                s[nf][half*2]   = p0;
                s[nf][half*2+1] = p1;
                lsum += p0 + p1;
            }
            lsum += __shfl_xor_sync(0xffffffffu, lsum, 1);
            lsum += __shfl_xor_sync(0xffffffffu, lsum, 2);
            l_i[half] = l_i[half] * corr + lsum;
            m_i[half] = m_new;
            #pragma unroll
            for (int nf = 0; nf < 16; nf++) {
                o[nf][half*2]   *= corr;
                o[nf][half*2+1] *= corr;
            }
        }

        // P -> smem (tf32 bits)
        #pragma unroll
        for (int nf = 0; nf < 8; nf++) {
            int col = nf*8 + 2*t4;
            Pw[g*68 + col]     = f2tf(s[nf][0]);
            Pw[g*68 + col + 1] = f2tf(s[nf][1]);
            Pw[(g+8)*68 + col]     = f2tf(s[nf][2]);
            Pw[(g+8)*68 + col + 1] = f2tf(s[nf][3]);
        }

        cp_wait0();          // V(kt) landed
        __syncthreads();

        // Prefetch K(kt+1) under O-compute
        if (kt + 1 < Sc/64) {
            #pragma unroll
            for (int i = 0; i < 8; i++) {
                int c = tid + i*256;
                int row = c >> 5, col = (c & 31) * 4;
                cp16(&Ks[row*132 + col], Kg + (size_t)(kt+1)*8192 + row*128 + col);
            }
        }
        cp_commit();

        // O += P @ V
        #pragma unroll 2
        for (int ks = 0; ks < 8; ks++) {
            unsigned a[4];
            a[0] = Pw[g*68     + ks*8 + t4];
            a[1] = Pw[(g+8)*68 + ks*8 + t4];
            a[2] = Pw[g*68     + ks*8 + t4 + 4];
            a[3] = Pw[(g+8)*68 + ks*8 + t4 + 4];
            #pragma unroll
            for (int nf = 0; nf < 16; nf++) {
                unsigned b[2];
                b[0] = Vs[(ks*8+t4)*136   + nf*8 + g];
                b[1] = Vs[(ks*8+t4+4)*136 + nf*8 + g];
                mma_tf32(o[nf], a, b);
            }
        }

        cp_wait0();          // K(kt+1) landed
        __syncthreads();
    }

    // Epilogue: normalize, write [b, s, h*HD + d] fp32
    int b = bh / Hc, h = bh % Hc;
    float inv0 = 1.f / l_i[0], inv1 = 1.f / l_i[1];
    #pragma unroll
    for (int nf = 0; nf < 16; nf++) {
        int d = nf*8 + 2*t4;
        int r0 = qb*128 + rbase + g;
        float* p0 = g_attn + (((size_t)(b*Sc + r0)) << 11) + h*128 + d;
        *(float2*)p0 = make_float2(o[nf][0]*inv0, o[nf][1]*inv0);
        float* p1 = g_attn + (((size_t)(b*Sc + r0 + 8)) << 11) + h*128 + d;
        *(float2*)p1 = make_float2(o[nf][2]*inv1, o[nf][3]*inv1);
    }
}

// ---------------------------------------------------------------------------
extern "C" void kernel_launch(void* const* d_in, const int* in_sizes, int n_in,
                              void* d_out, int out_size) {
    const float *x = nullptr, *wqkv = nullptr, *wout = nullptr;
    for (int i = 0; i < n_in; i++) {
        int sz = in_sizes[i];
        if (sz == Bc*Sc*Ec)     x    = (const float*)d_in[i];
        else if (sz == Ec*3*Ac) wqkv = (const float*)d_in[i];
        else if (sz == Ac*Ec)   wout = (const float*)d_in[i];
    }
    float* out = (float*)d_out;
    const int M = Bc * Sc;  // 4096

    rope_table_kernel<<<(Sc*(HDc/2) + 255)/256, 256>>>();

    gemm_tc<<<dim3(3*Ac/128, M/128), 256>>>(x, wqkv, nullptr, M, 3*Ac, Ec, 1);

    static int smem_set = 0;
    if (!smem_set) {
        cudaFuncSetAttribute(flash_tc,
            cudaFuncAttributeMaxDynamicSharedMemorySize, 180*1024);
        smem_set = 1;
    }
    size_t smem = (128*132 + 64*132 + 64*136 + 8*16*68) * sizeof(unsigned);
    flash_tc<<<dim3(Sc/128, Bc*Hc), 256, smem>>>();

    gemm_tc<<<dim3(Ec/128, M/128), 256>>>(nullptr, wout, out, M, Ec, Ac, 0);
}

// round 4
// speedup vs baseline: 3.5430x; 1.0660x over previous
#include <cuda_runtime.h>
#include <math.h>

#define Bc  2
#define Sc  2048
#define Ec  2048
#define Ac  2048
#define Hc  16
#define HDc 128

// Scratch (device globals). All tf32 BIT PATTERNS except noted.
__device__ unsigned g_Q[Bc*Hc*Sc*HDc];
__device__ unsigned g_K[Bc*Hc*Sc*HDc];
__device__ unsigned g_V[Bc*Hc*Sc*HDc];
__device__ unsigned g_attn[Bc*Sc*Ac];        // attention out, tf32 bits
__device__ unsigned g_x_tf[Bc*Sc*Ec];
__device__ unsigned g_wqkv_tf[Ec*3*Ac];
__device__ unsigned g_wout_tf[Ac*Ec];
__device__ float    g_cos[Sc*(HDc/2)];
__device__ float    g_sin[Sc*(HDc/2)];

// ---------------------------------------------------------------------------
__device__ __forceinline__ unsigned f2tf(float f) {
    unsigned u; asm("cvt.rna.tf32.f32 %0, %1;" : "=r"(u) : "f"(f)); return u;
}
__device__ __forceinline__ void mma_tf32(float* c, const unsigned* a, const unsigned* b) {
    asm volatile("mma.sync.aligned.m16n8k8.row.col.f32.tf32.tf32.f32 "
        "{%0,%1,%2,%3}, {%4,%5,%6,%7}, {%8,%9}, {%0,%1,%2,%3};"
        : "+f"(c[0]), "+f"(c[1]), "+f"(c[2]), "+f"(c[3])
        : "r"(a[0]), "r"(a[1]), "r"(a[2]), "r"(a[3]), "r"(b[0]), "r"(b[1]));
}
__device__ __forceinline__ void cp16(unsigned* smem_dst, const void* gsrc) {
    unsigned d = (unsigned)__cvta_generic_to_shared(smem_dst);
    asm volatile("cp.async.cg.shared.global [%0], [%1], 16;" :: "r"(d), "l"(gsrc));
}
__device__ __forceinline__ void cp_commit() {
    asm volatile("cp.async.commit_group;");
}

// ---------------------------------------------------------------------------
__global__ void rope_table_kernel() {
    int idx = blockIdx.x * blockDim.x + threadIdx.x;
    if (idx >= Sc * (HDc/2)) return;
    int pos = idx / (HDc/2);
    int j   = idx % (HDc/2);
    double inv = pow(10000.0, -((double)(2*j)) / (double)HDc);
    double a = (double)pos * inv;
    g_cos[idx] = (float)cos(a);
    g_sin[idx] = (float)sin(a);
}

// One-pass fp32 -> tf32-bits converter (vectorized)
__global__ void cvt_kernel(const float4* __restrict__ src,
                           uint4* __restrict__ dst, int n4) {
    int i = blockIdx.x * blockDim.x + threadIdx.x;
    if (i < n4) {
        float4 v = src[i];
        dst[i] = make_uint4(f2tf(v.x), f2tf(v.y), f2tf(v.z), f2tf(v.w));
    }
}

// ---------------------------------------------------------------------------
// tf32 tensor-core GEMM, 128x128 tile, BK=16, 512 threads (16 warps, 32x32
// warp tile), 3-stage cp.async pipeline. Operands are tf32 bits in global.
// mode 1: A=g_x_tf, B=g_wqkv_tf, RoPE scatter epilogue -> g_Q/g_K/g_V.
// mode 0: A=g_attn,  B=g_wout_tf, fp32 store to C.
// ---------------------------------------------------------------------------
#define BK 16
#define STAGES 3
#define AS_W 20
#define BS_W 136
#define AS_SZ (128*AS_W)
#define BS_SZ (BK*BS_W)

__global__ __launch_bounds__(512, 1) void gemm_tc(
    float* __restrict__ C, int N, int K, int mode)
{
    extern __shared__ unsigned smem[];
    unsigned* As = smem;                       // STAGES x AS_SZ
    unsigned* Bs = smem + STAGES*AS_SZ;        // STAGES x BS_SZ

    const unsigned* Ag = mode ? g_x_tf : g_attn;
    const unsigned* Bg = mode ? g_wqkv_tf : g_wout_tf;

    int tid  = threadIdx.x;
    int warp = tid >> 5, lane = tid & 31;
    int g = lane >> 2, t4 = lane & 3;
    int wm = warp >> 2, wn = warp & 3;         // 4x4 warp grid
    int m0 = blockIdx.y * 128, n0 = blockIdx.x * 128;

    float acc[2][4][4];
    #pragma unroll
    for (int i = 0; i < 2; i++)
        #pragma unroll
        for (int j = 0; j < 4; j++)
            #pragma unroll
            for (int r = 0; r < 4; r++) acc[i][j][r] = 0.f;

    int arow = tid >> 2, ac4 = (tid & 3) * 4;   // A tile: 128 x 16
    int brow = tid >> 5, bc4 = (tid & 31) * 4;  // B tile: 16 x 128

    const unsigned* Aptr = Ag + (size_t)(m0 + arow) * K + ac4;
    const unsigned* Bptr = Bg + (size_t)brow * N + n0 + bc4;

    int T = K / BK;

    #pragma unroll
    for (int s = 0; s < STAGES-1; s++) {
        cp16(&As[s*AS_SZ + arow*AS_W + ac4], Aptr + s*BK);
        cp16(&Bs[s*BS_SZ + brow*BS_W + bc4], Bptr + (size_t)s*BK*N);
        cp_commit();
    }

    for (int it = 0; it < T; it++) {
        asm volatile("cp.async.wait_group %0;" :: "n"(STAGES-2));
        __syncthreads();

        int nxt = it + STAGES - 1;
        if (nxt < T) {
            int st = nxt % STAGES;
            cp16(&As[st*AS_SZ + arow*AS_W + ac4], Aptr + nxt*BK);
            cp16(&Bs[st*BS_SZ + brow*BS_W + bc4], Bptr + (size_t)nxt*BK*N);
        }
        cp_commit();

        const unsigned* Ac_ = &As[(it % STAGES) * AS_SZ];
        const unsigned* Bc_ = &Bs[(it % STAGES) * BS_SZ];
        #pragma unroll
        for (int kk = 0; kk < BK; kk += 8) {
            unsigned a[2][4], b[4][2];
            #pragma unroll
            for (int mf = 0; mf < 2; mf++) {
                int r = wm*32 + mf*16 + g;
                a[mf][0] = Ac_[r*AS_W + kk + t4];
                a[mf][1] = Ac_[(r+8)*AS_W + kk + t4];
                a[mf][2] = Ac_[r*AS_W + kk + t4 + 4];
                a[mf][3] = Ac_[(r+8)*AS_W + kk + t4 + 4];
            }
            #pragma unroll
            for (int nf = 0; nf < 4; nf++) {
                int c = wn*32 + nf*8 + g;
                b[nf][0] = Bc_[(kk+t4)*BS_W + c];
                b[nf][1] = Bc_[(kk+t4+4)*BS_W + c];
            }
            #pragma unroll
            for (int mf = 0; mf < 2; mf++)
                #pragma unroll
                for (int nf = 0; nf < 4; nf++)
                    mma_tf32(acc[mf][nf], a[mf], b[nf]);
        }
    }

    if (mode == 0) {
        #pragma unroll
        for (int mf = 0; mf < 2; mf++)
            #pragma unroll
            for (int nf = 0; nf < 4; nf++) {
                int row = m0 + wm*32 + mf*16 + g;
                int col = n0 + wn*32 + nf*8 + 2*t4;
                *(float2*)(C + (size_t)row*N + col) =
                    make_float2(acc[mf][nf][0], acc[mf][nf][1]);
                *(float2*)(C + (size_t)(row+8)*N + col) =
                    make_float2(acc[mf][nf][2], acc[mf][nf][3]);
            }
    } else {
        #pragma unroll
        for (int nf = 0; nf < 4; nf++) {
            int n   = n0 + wn*32 + nf*8 + 2*t4;
            int t   = n / Ac;
            int rem = n % Ac;
            int h   = rem >> 7;
            int d   = rem & 127;
            int j   = d >> 1;
            unsigned* dst = (t == 0) ? g_Q : (t == 1) ? g_K : g_V;
            #pragma unroll
            for (int mf = 0; mf < 2; mf++) {
                #pragma unroll
                for (int half = 0; half < 2; half++) {
                    int row = m0 + wm*32 + mf*16 + g + half*8;
                    int b = row >> 11, s = row & 2047;
                    float c0 = acc[mf][nf][half*2];
                    float c1 = acc[mf][nf][half*2 + 1];
                    unsigned* p = dst + (((size_t)(b*Hc + h)*Sc + s) << 7) + d;
                    if (t == 2) { p[0] = f2tf(c0); p[1] = f2tf(c1); }
                    else {
                        float cs = g_cos[s*64 + j], sn = g_sin[s*64 + j];
                        p[0] = f2tf(c0*cs - c1*sn);
                        p[1] = f2tf(c0*sn + c1*cs);
                    }
                }
            }
        }
    }
}

// ---------------------------------------------------------------------------
// Flash attention (tf32 mma). Q/K/V in global are tf32 bits.
// cp.async phase pipeline: V(kt) under S-compute, K(kt+1) under O-compute.
// ---------------------------------------------------------------------------
__global__ __launch_bounds__(256, 1) void flash_tc() {
    extern __shared__ unsigned sm[];
    unsigned* Qs = sm;                 // [128][132]
    unsigned* Ks = Qs + 128*132;       // [64][132]
    unsigned* Vs = Ks + 64*132;        // [64][136]
    unsigned* Ps = Vs + 64*136;        // 8 warps x [16][68]

    int tid  = threadIdx.x;
    int warp = tid >> 5, lane = tid & 31;
    int g = lane >> 2, t4 = lane & 3;
    int qb = blockIdx.x, bh = blockIdx.y;

    const unsigned* Qg = g_Q + (((size_t)bh*Sc + qb*128) << 7);
    const unsigned* Kg = g_K + ((size_t)bh*Sc << 7);
    const unsigned* Vg = g_V + ((size_t)bh*Sc << 7);

    #pragma unroll
    for (int i = 0; i < 16; i++) {
        int c = tid + i*256;
        int row = c >> 5, col = (c & 31) * 4;
        *(uint4*)&Qs[row*132 + col] = *(const uint4*)&Qg[row*128 + col];
    }

    #pragma unroll
    for (int i = 0; i < 8; i++) {
        int c = tid + i*256;
        int row = c >> 5, col = (c & 31) * 4;
        cp16(&Ks[row*132 + col], Kg + row*128 + col);
    }
    cp_commit();

    float m_i[2] = {-INFINITY, -INFINITY}, l_i[2] = {0.f, 0.f};
    float o[16][4];
    #pragma unroll
    for (int nf = 0; nf < 16; nf++)
        #pragma unroll
        for (int r = 0; r < 4; r++) o[nf][r] = 0.f;

    const float scale = 0.08838834764831845f;
    int rbase = warp * 16;
    unsigned* Pw = Ps + warp * 16 * 68;

    asm volatile("cp.async.wait_group 0;");
    __syncthreads();

    for (int kt = 0; kt < Sc/64; kt++) {
        #pragma unroll
        for (int i = 0; i < 8; i++) {
            int c = tid + i*256;
            int row = c >> 5, col = (c & 31) * 4;
            cp16(&Vs[row*136 + col], Vg + (size_t)kt*8192 + row*128 + col);
        }
        cp_commit();

        float s[8][4];
        #pragma unroll
        for (int nf = 0; nf < 8; nf++)
            #pragma unroll
            for (int r = 0; r < 4; r++) s[nf][r] = 0.f;

        #pragma unroll 4
        for (int ks = 0; ks < 16; ks++) {
            unsigned a[4];
            a[0] = Qs[(rbase+g)*132   + ks*8 + t4];
            a[1] = Qs[(rbase+g+8)*132 + ks*8 + t4];
            a[2] = Qs[(rbase+g)*132   + ks*8 + t4 + 4];
            a[3] = Qs[(rbase+g+8)*132 + ks*8 + t4 + 4];
            #pragma unroll
            for (int nf = 0; nf < 8; nf++) {
                unsigned b[2];
                b[0] = Ks[(nf*8+g)*132 + ks*8 + t4];
                b[1] = Ks[(nf*8+g)*132 + ks*8 + t4 + 4];
                mma_tf32(s[nf], a, b);
            }
        }

        #pragma unroll
        for (int half = 0; half < 2; half++) {
            float mx = -INFINITY;
            #pragma unroll
            for (int nf = 0; nf < 8; nf++)
                mx = fmaxf(mx, fmaxf(s[nf][half*2], s[nf][half*2+1]));
            mx *= scale;
            mx = fmaxf(mx, __shfl_xor_sync(0xffffffffu, mx, 1));
            mx = fmaxf(mx, __shfl_xor_sync(0xffffffffu, mx, 2));
            float m_new = fmaxf(m_i[half], mx);
            float corr  = __expf(m_i[half] - m_new);
            float lsum  = 0.f;
            #pragma unroll
            for (int nf = 0; nf < 8; nf++) {
                float p0 = __expf(s[nf][half*2]   * scale - m_new);
                float p1 = __expf(s[nf][half*2+1] * scale - m_new);
                s[nf][half*2]   = p0;
                s[nf][half*2+1] = p1;
                lsum += p0 + p1;
            }
            lsum += __shfl_xor_sync(0xffffffffu, lsum, 1);
            lsum += __shfl_xor_sync(0xffffffffu, lsum, 2);
            l_i[half] = l_i[half] * corr + lsum;
            m_i[half] = m_new;
            #pragma unroll
            for (int nf = 0; nf < 16; nf++) {
                o[nf][half*2]   *= corr;
                o[nf][half*2+1] *= corr;
            }
        }

        #pragma unroll
        for (int nf = 0; nf < 8; nf++) {
            int col = nf*8 + 2*t4;
            Pw[g*68 + col]     = f2tf(s[nf][0]);
            Pw[g*68 + col + 1] = f2tf(s[nf][1]);
            Pw[(g+8)*68 + col]     = f2tf(s[nf][2]);
            Pw[(g+8)*68 + col + 1] = f2tf(s[nf][3]);
        }

        asm volatile("cp.async.wait_group 0;");
        __syncthreads();

        if (kt + 1 < Sc/64) {
            #pragma unroll
            for (int i = 0; i < 8; i++) {
                int c = tid + i*256;
                int row = c >> 5, col = (c & 31) * 4;
                cp16(&Ks[row*132 + col], Kg + (size_t)(kt+1)*8192 + row*128 + col);
            }
        }
        cp_commit();

        #pragma unroll 2
        for (int ks = 0; ks < 8; ks++) {
            unsigned a[4];
            a[0] = Pw[g*68     + ks*8 + t4];
            a[1] = Pw[(g+8)*68 + ks*8 + t4];
            a[2] = Pw[g*68     + ks*8 + t4 + 4];
            a[3] = Pw[(g+8)*68 + ks*8 + t4 + 4];
            #pragma unroll
            for (int nf = 0; nf < 16; nf++) {
                unsigned b[2];
                b[0] = Vs[(ks*8+t4)*136   + nf*8 + g];
                b[1] = Vs[(ks*8+t4+4)*136 + nf*8 + g];
                mma_tf32(o[nf], a, b);
            }
        }

        asm volatile("cp.async.wait_group 0;");
        __syncthreads();
    }

    // Epilogue: normalize, write tf32 bits to g_attn in [b, s, h*HD+d]
    int b = bh / Hc, h = bh % Hc;
    float inv0 = 1.f / l_i[0], inv1 = 1.f / l_i[1];
    #pragma unroll
    for (int nf = 0; nf < 16; nf++) {
        int d = nf*8 + 2*t4;
        int r0 = qb*128 + rbase + g;
        unsigned* p0 = g_attn + (((size_t)(b*Sc + r0)) << 11) + h*128 + d;
        p0[0] = f2tf(o[nf][0]*inv0);
        p0[1] = f2tf(o[nf][1]*inv0);
        unsigned* p1 = g_attn + (((size_t)(b*Sc + r0 + 8)) << 11) + h*128 + d;
        p1[0] = f2tf(o[nf][2]*inv1);
        p1[1] = f2tf(o[nf][3]*inv1);
    }
}

// ---------------------------------------------------------------------------
extern "C" void kernel_launch(void* const* d_in, const int* in_sizes, int n_in,
                              void* d_out, int out_size) {
    const float *x = nullptr, *wqkv = nullptr, *wout = nullptr;
    for (int i = 0; i < n_in; i++) {
        int sz = in_sizes[i];
        if (sz == Bc*Sc*Ec)     x    = (const float*)d_in[i];
        else if (sz == Ec*3*Ac) wqkv = (const float*)d_in[i];
        else if (sz == Ac*Ec)   wout = (const float*)d_in[i];
    }
    float* out = (float*)d_out;
    const int M = Bc * Sc;  // 4096

    static int attr_set = 0;
    if (!attr_set) {
        cudaFuncSetAttribute(gemm_tc,
            cudaFuncAttributeMaxDynamicSharedMemorySize, 64*1024);
        cudaFuncSetAttribute(flash_tc,
            cudaFuncAttributeMaxDynamicSharedMemorySize, 180*1024);
        attr_set = 1;
    }

    rope_table_kernel<<<(Sc*(HDc/2) + 255)/256, 256>>>();

    // Pre-convert inputs to tf32 bits (device symbol addresses via kernels)
    unsigned* dxt; cudaGetSymbolAddress((void**)&dxt, g_x_tf);
    unsigned* dwq; cudaGetSymbolAddress((void**)&dwq, g_wqkv_tf);
    unsigned* dwo; cudaGetSymbolAddress((void**)&dwo, g_wout_tf);
    {
        int n4 = Bc*Sc*Ec/4;
        cvt_kernel<<<(n4+255)/256, 256>>>((const float4*)x, (uint4*)dxt, n4);
        n4 = Ec*3*Ac/4;
        cvt_kernel<<<(n4+255)/256, 256>>>((const float4*)wqkv, (uint4*)dwq, n4);
        n4 = Ac*Ec/4;
        cvt_kernel<<<(n4+255)/256, 256>>>((const float4*)wout, (uint4*)dwo, n4);
    }

    size_t gsmem = (size_t)(STAGES*AS_SZ + STAGES*BS_SZ) * sizeof(unsigned);

    // QKV GEMM + RoPE
    gemm_tc<<<dim3(3*Ac/128, M/128), 512, gsmem>>>(nullptr, 3*Ac, Ec, 1);

    // Flash attention
    size_t fsmem = (128*132 + 64*132 + 64*136 + 8*16*68) * sizeof(unsigned);
    flash_tc<<<dim3(Sc/128, Bc*Hc), 256, fsmem>>>();

    // Output projection
    gemm_tc<<<dim3(Ec/128, M/128), 512, gsmem>>>(out, Ec, Ac, 0);
}

// round 6
// speedup vs baseline: 8.0750x; 2.2792x over previous
#include <cuda_runtime.h>
#include <cuda_fp16.h>
#include <math.h>
#include <stdint.h>

#define Bc  2
#define Sc  2048
#define Ec  2048
#define Ac  2048
#define Hc  16
#define HDc 128

// Scratch (device globals), fp16 operands.
__device__ __half g_Q[Bc*Hc*Sc*HDc];
__device__ __half g_K[Bc*Hc*Sc*HDc];
__device__ __half g_V[Bc*Hc*Sc*HDc];
__device__ __half g_attn[Bc*Sc*Ac];          // attention out (fp16)
__device__ __half g_x_h[Bc*Sc*Ec];           // x fp16 [4096][2048]
__device__ __half g_wqkv_t[3*Ac*Ec];         // W_qkv^T fp16 [6144][2048]
__device__ __half g_wout_t[Ec*Ac];           // W_out^T fp16 [2048][2048]
__device__ float  g_cos[Sc*(HDc/2)];
__device__ float  g_sin[Sc*(HDc/2)];

// ---------------------------------------------------------------------------
__device__ __forceinline__ void mma_h(float* c, const unsigned* a, const unsigned* b) {
    asm volatile("mma.sync.aligned.m16n8k16.row.col.f32.f16.f16.f32 "
        "{%0,%1,%2,%3}, {%4,%5,%6,%7}, {%8,%9}, {%0,%1,%2,%3};"
        : "+f"(c[0]), "+f"(c[1]), "+f"(c[2]), "+f"(c[3])
        : "r"(a[0]), "r"(a[1]), "r"(a[2]), "r"(a[3]), "r"(b[0]), "r"(b[1]));
}
__device__ __forceinline__ void ldm_x4(unsigned& r0, unsigned& r1, unsigned& r2,
                                       unsigned& r3, unsigned addr) {
    asm volatile("ldmatrix.sync.aligned.m8n8.x4.shared.b16 {%0,%1,%2,%3}, [%4];"
        : "=r"(r0), "=r"(r1), "=r"(r2), "=r"(r3) : "r"(addr));
}
__device__ __forceinline__ void ldm_x4_t(unsigned& r0, unsigned& r1, unsigned& r2,
                                         unsigned& r3, unsigned addr) {
    asm volatile("ldmatrix.sync.aligned.m8n8.x4.trans.shared.b16 {%0,%1,%2,%3}, [%4];"
        : "=r"(r0), "=r"(r1), "=r"(r2), "=r"(r3) : "r"(addr));
}
__device__ __forceinline__ void cp16(void* smem_dst, const void* gsrc) {
    unsigned d = (unsigned)__cvta_generic_to_shared(smem_dst);
    asm volatile("cp.async.cg.shared.global [%0], [%1], 16;" :: "r"(d), "l"(gsrc));
}
__device__ __forceinline__ void cp_commit() { asm volatile("cp.async.commit_group;"); }
__device__ __forceinline__ unsigned smem_u32(const void* p) {
    return (unsigned)__cvta_generic_to_shared(p);
}

// ---------------------------------------------------------------------------
__global__ void rope_table_kernel() {
    int idx = blockIdx.x * blockDim.x + threadIdx.x;
    if (idx >= Sc * (HDc/2)) return;
    int pos = idx / (HDc/2);
    int j   = idx % (HDc/2);
    double inv = pow(10000.0, -((double)(2*j)) / (double)HDc);
    double a = (double)pos * inv;
    g_cos[idx] = (float)cos(a);
    g_sin[idx] = (float)sin(a);
}

__global__ void cvt_h(const float4* __restrict__ src, __half2* __restrict__ dst, int n4) {
    int i = blockIdx.x * blockDim.x + threadIdx.x;
    if (i < n4) {
        float4 v = src[i];
        dst[2*i]   = __floats2half2_rn(v.x, v.y);
        dst[2*i+1] = __floats2half2_rn(v.z, v.w);
    }
}

// Transpose + fp16 convert: src fp32 [R][C] -> dst fp16 [C][R]
__global__ __launch_bounds__(256) void transpose_cvt_h(
    const float* __restrict__ src, __half* __restrict__ dst, int R, int Ccols) {
    __shared__ __half tile[32][33];
    int c0 = blockIdx.x*32, r0 = blockIdx.y*32;
    int tx = threadIdx.x & 31, ty = threadIdx.x >> 5;
    #pragma unroll
    for (int i = 0; i < 4; i++)
        tile[ty + 8*i][tx] = __float2half(src[(size_t)(r0 + ty + 8*i)*Ccols + c0 + tx]);
    __syncthreads();
    #pragma unroll
    for (int i = 0; i < 4; i++)
        dst[(size_t)(c0 + ty + 8*i)*R + r0 + tx] = tile[tx][ty + 8*i];
}

// ---------------------------------------------------------------------------
// fp16 tensor-core GEMM: 128x128 tile, BK=32, 8 warps (2x4, warp tile 64x32),
// 3-stage cp.async, ldmatrix fragments. Both operands K-major fp16.
// mode 1: A=g_x_h, B=g_wqkv_t -> RoPE scatter to g_Q/g_K/g_V (fp16).
// mode 0: A=g_attn, B=g_wout_t -> fp32 C.
// ---------------------------------------------------------------------------
#define AW 40                         // padded row width (halves)
#define STG_H (2*128*AW)              // halves per stage (A+B)
#define STG_B (STG_H*2)               // bytes per stage

__global__ __launch_bounds__(256, 2) void gemm_h(
    float* __restrict__ C, int N, int K, int mode)
{
    extern __shared__ __half hs[];

    const __half* Ag = mode ? g_x_h : g_attn;
    const __half* Bg = mode ? g_wqkv_t : g_wout_t;

    int tid  = threadIdx.x;
    int warp = tid >> 5, lane = tid & 31;
    int lr = lane & 7, lq = lane >> 3;
    int g = lane >> 2, t4 = lane & 3;
    int wm = warp >> 2, wn = warp & 3;
    int m0 = blockIdx.y * 128, n0 = blockIdx.x * 128;
    unsigned sbase = smem_u32(hs);

    float acc[4][4][4];
    #pragma unroll
    for (int i = 0; i < 4; i++)
        #pragma unroll
        for (int j = 0; j < 4; j++)
            #pragma unroll
            for (int r = 0; r < 4; r++) acc[i][j][r] = 0.f;

    int T = K / 32;

    // stage loader: A tile 128x32, B tile 128x32 (both K-major)
    auto load_stage = [&](int s, int kt) {
        __half* As = hs + s*STG_H;
        __half* Bs = As + 128*AW;
        #pragma unroll
        for (int i = 0; i < 2; i++) {
            int c = tid + i*256;
            int row = c >> 2, kc = (c & 3) * 8;
            cp16(As + row*AW + kc, Ag + (size_t)(m0+row)*K + kt*32 + kc);
            cp16(Bs + row*AW + kc, Bg + (size_t)(n0+row)*K + kt*32 + kc);
        }
        cp_commit();
    };

    load_stage(0, 0);
    load_stage(1, 1);

    for (int it = 0; it < T; it++) {
        asm volatile("cp.async.wait_group 1;");
        __syncthreads();
        if (it + 2 < T) load_stage((it+2) % 3, it+2);
        else cp_commit();

        unsigned abase = sbase + (it % 3) * STG_B;
        unsigned bbase = abase + 128*AW*2;

        #pragma unroll
        for (int kk = 0; kk < 32; kk += 16) {
            unsigned a[4][4], b[4][2];
            #pragma unroll
            for (int mf = 0; mf < 4; mf++) {
                int row  = wm*64 + mf*16 + (lq & 1)*8 + lr;
                int kcol = kk + (lq >> 1)*8;
                ldm_x4(a[mf][0], a[mf][1], a[mf][2], a[mf][3],
                       abase + (row*AW + kcol)*2);
            }
            #pragma unroll
            for (int np = 0; np < 2; np++) {
                int row  = wn*32 + np*16 + (lq >> 1)*8 + lr;
                int kcol = kk + (lq & 1)*8;
                ldm_x4(b[np*2][0], b[np*2][1], b[np*2+1][0], b[np*2+1][1],
                       bbase + (row*AW + kcol)*2);
            }
            #pragma unroll
            for (int mf = 0; mf < 4; mf++)
                #pragma unroll
                for (int nf = 0; nf < 4; nf++)
                    mma_h(acc[mf][nf], a[mf], b[nf]);
        }
    }

    if (mode == 0) {
        #pragma unroll
        for (int mf = 0; mf < 4; mf++)
            #pragma unroll
            for (int nf = 0; nf < 4; nf++) {
                int row = m0 + wm*64 + mf*16 + g;
                int col = n0 + wn*32 + nf*8 + 2*t4;
                *(float2*)(C + (size_t)row*N + col) =
                    make_float2(acc[mf][nf][0], acc[mf][nf][1]);
                *(float2*)(C + (size_t)(row+8)*N + col) =
                    make_float2(acc[mf][nf][2], acc[mf][nf][3]);
            }
    } else {
        #pragma unroll
        for (int nf = 0; nf < 4; nf++) {
            int n   = n0 + wn*32 + nf*8 + 2*t4;
            int t   = n / 2048;
            int rem = n % 2048;
            int h   = rem >> 7;
            int d   = rem & 127;
            int j   = d >> 1;
            __half* dst = (t == 0) ? g_Q : (t == 1) ? g_K : g_V;
            #pragma unroll
            for (int mf = 0; mf < 4; mf++) {
                #pragma unroll
                for (int half = 0; half < 2; half++) {
                    int row = m0 + wm*64 + mf*16 + g + half*8;
                    int b = row >> 11, s = row & 2047;
                    float c0 = acc[mf][nf][half*2];
                    float c1 = acc[mf][nf][half*2 + 1];
                    __half2* p = (__half2*)(dst
                        + (((size_t)(b*Hc + h)*Sc + s) << 7) + d);
                    if (t == 2) *p = __floats2half2_rn(c0, c1);
                    else {
                        float cs = g_cos[s*64 + j], sn = g_sin[s*64 + j];
                        *p = __floats2half2_rn(c0*cs - c1*sn, c0*sn + c1*cs);
                    }
                }
            }
        }
    }
}

// ---------------------------------------------------------------------------
// fp16 flash attention. BM=128, BN=64, 256 threads (8 warps x 16 q-rows).
// ldmatrix everywhere; fp32 scores/softmax/O-accum; P stored fp16.
// ---------------------------------------------------------------------------
#define QW 136
#define PW 72

__global__ __launch_bounds__(256, 1) void flash_h() {
    extern __shared__ __half sh[];
    __half* Qs = sh;                   // [128][136]
    __half* Ks = Qs + 128*QW;          // [64][136]
    __half* Vs = Ks + 64*QW;           // [64][136]
    __half* Ps = Vs + 64*QW;           // 8 x [16][72]

    int tid  = threadIdx.x;
    int warp = tid >> 5, lane = tid & 31;
    int lr = lane & 7, lq = lane >> 3;
    int g = lane >> 2, t4 = lane & 3;
    int qb = blockIdx.x, bh = blockIdx.y;

    const __half* Qg = g_Q + (((size_t)bh*Sc + qb*128) << 7);
    const __half* Kg = g_K + ((size_t)bh*Sc << 7);
    const __half* Vg = g_V + ((size_t)bh*Sc << 7);

    unsigned qbase = smem_u32(Qs);
    unsigned kbase = smem_u32(Ks);
    unsigned vbase = smem_u32(Vs);
    unsigned pbase = smem_u32(Ps) + warp*16*PW*2;

    // Q: 128 rows x 128 halves = 2048 16B chunks
    #pragma unroll
    for (int i = 0; i < 8; i++) {
        int c = tid + i*256;
        int row = c >> 4, kc = (c & 15) * 8;
        cp16(Qs + row*QW + kc, Qg + row*128 + kc);
    }
    // K(0): 1024 chunks
    #pragma unroll
    for (int i = 0; i < 4; i++) {
        int c = tid + i*256;
        int row = c >> 4, kc = (c & 15) * 8;
        cp16(Ks + row*QW + kc, Kg + row*128 + kc);
    }
    cp_commit();

    float m_i[2] = {-INFINITY, -INFINITY}, l_i[2] = {0.f, 0.f};
    float o[16][4];
    #pragma unroll
    for (int nf = 0; nf < 16; nf++)
        #pragma unroll
        for (int r = 0; r < 4; r++) o[nf][r] = 0.f;

    const float scale = 0.08838834764831845f;
    int rbase = warp * 16;

    asm volatile("cp.async.wait_group 0;");
    __syncthreads();

    for (int kt = 0; kt < Sc/64; kt++) {
        // prefetch V(kt) under S-compute
        #pragma unroll
        for (int i = 0; i < 4; i++) {
            int c = tid + i*256;
            int row = c >> 4, kc = (c & 15) * 8;
            cp16(Vs + row*QW + kc, Vg + (size_t)kt*8192 + row*128 + kc);
        }
        cp_commit();

        // S = Q @ K^T  (8 k16-steps over d=128)
        float s[8][4];
        #pragma unroll
        for (int nf = 0; nf < 8; nf++)
            #pragma unroll
            for (int r = 0; r < 4; r++) s[nf][r] = 0.f;

        #pragma unroll
        for (int ks = 0; ks < 8; ks++) {
            int kd = ks*16;
            unsigned a[4], b[8][2];
            {
                int row  = rbase + (lq & 1)*8 + lr;
                int kcol = kd + (lq >> 1)*8;
                ldm_x4(a[0], a[1], a[2], a[3], qbase + (row*QW + kcol)*2);
            }
            #pragma unroll
            for (int np = 0; np < 4; np++) {
                int row  = np*16 + (lq >> 1)*8 + lr;
                int kcol = kd + (lq & 1)*8;
                ldm_x4(b[np*2][0], b[np*2][1], b[np*2+1][0], b[np*2+1][1],
                       kbase + (row*QW + kcol)*2);
            }
            #pragma unroll
            for (int nf = 0; nf < 8; nf++) mma_h(s[nf], a, b[nf]);
        }

        // online softmax (rows rbase+g, rbase+g+8)
        #pragma unroll
        for (int half = 0; half < 2; half++) {
            float mx = -INFINITY;
            #pragma unroll
            for (int nf = 0; nf < 8; nf++)
                mx = fmaxf(mx, fmaxf(s[nf][half*2], s[nf][half*2+1]));
            mx *= scale;
            mx = fmaxf(mx, __shfl_xor_sync(0xffffffffu, mx, 1));
            mx = fmaxf(mx, __shfl_xor_sync(0xffffffffu, mx, 2));
            float m_new = fmaxf(m_i[half], mx);
            float corr  = __expf(m_i[half] - m_new);
            float lsum  = 0.f;
            #pragma unroll
            for (int nf = 0; nf < 8; nf++) {
                float p0 = __expf(s[nf][half*2]   * scale - m_new);
                float p1 = __expf(s[nf][half*2+1] * scale - m_new);
                s[nf][half*2]   = p0;
                s[nf][half*2+1] = p1;
                lsum += p0 + p1;
            }
            lsum += __shfl_xor_sync(0xffffffffu, lsum, 1);
            lsum += __shfl_xor_sync(0xffffffffu, lsum, 2);
            l_i[half] = l_i[half] * corr + lsum;
            m_i[half] = m_new;
            #pragma unroll
            for (int nf = 0; nf < 16; nf++) {
                o[nf][half*2]   *= corr;
                o[nf][half*2+1] *= corr;
            }
        }

        // P -> smem (fp16)
        __half* Pw = Ps + warp*16*PW;
        #pragma unroll
        for (int nf = 0; nf < 8; nf++) {
            int col = nf*8 + 2*t4;
            *(__half2*)&Pw[g*PW + col]     = __floats2half2_rn(s[nf][0], s[nf][1]);
            *(__half2*)&Pw[(g+8)*PW + col] = __floats2half2_rn(s[nf][2], s[nf][3]);
        }

        asm volatile("cp.async.wait_group 0;");   // V(kt) landed
        __syncthreads();

        // prefetch K(kt+1) under O-compute
        if (kt + 1 < Sc/64) {
            #pragma unroll
            for (int i = 0; i < 4; i++) {
                int c = tid + i*256;
                int row = c >> 4, kc = (c & 15) * 8;
                cp16(Ks + row*QW + kc, Kg + (size_t)(kt+1)*8192 + row*128 + kc);
            }
        }
        cp_commit();

        // O += P @ V  (4 k16-steps over kv=64)
        #pragma unroll
        for (int ks = 0; ks < 4; ks++) {
            int kv = ks*16;
            unsigned a[4], b[16][2];
            {
                int row  = (lq & 1)*8 + lr;
                int kcol = kv + (lq >> 1)*8;
                ldm_x4(a[0], a[1], a[2], a[3], pbase + (row*PW + kcol)*2);
            }
            #pragma unroll
            for (int np = 0; np < 8; np++) {
                int row = kv + (lq & 1)*8 + lr;       // kv row
                int col = np*16 + (lq >> 1)*8;        // d col
                ldm_x4_t(b[np*2][0], b[np*2][1], b[np*2+1][0], b[np*2+1][1],
                         vbase + (row*QW + col)*2);
            }
            #pragma unroll
            for (int nf = 0; nf < 16; nf++) mma_h(o[nf], a, b[nf]);
        }

        asm volatile("cp.async.wait_group 0;");   // K(kt+1) landed
        __syncthreads();
    }

    // epilogue: normalize, write fp16 to g_attn [b, s, h*128+d]
    int b = bh / Hc, h = bh % Hc;
    float inv0 = 1.f / l_i[0], inv1 = 1.f / l_i[1];
    #pragma unroll
    for (int nf = 0; nf < 16; nf++) {
        int d = nf*8 + 2*t4;
        int r0 = qb*128 + rbase + g;
        __half2* p0 = (__half2*)(g_attn + (((size_t)(b*Sc + r0)) << 11) + h*128 + d);
        *p0 = __floats2half2_rn(o[nf][0]*inv0, o[nf][1]*inv0);
        __half2* p1 = (__half2*)(g_attn + (((size_t)(b*Sc + r0 + 8)) << 11) + h*128 + d);
        *p1 = __floats2half2_rn(o[nf][2]*inv1, o[nf][3]*inv1);
    }
}

// ---------------------------------------------------------------------------
extern "C" void kernel_launch(void* const* d_in, const int* in_sizes, int n_in,
                              void* d_out, int out_size) {
    const float *x = nullptr, *wqkv = nullptr, *wout = nullptr;
    for (int i = 0; i < n_in; i++) {
        int sz = in_sizes[i];
        if (sz == Bc*Sc*Ec)     x    = (const float*)d_in[i];
        else if (sz == Ec*3*Ac) wqkv = (const float*)d_in[i];
        else if (sz == Ac*Ec)   wout = (const float*)d_in[i];
    }
    float* out = (float*)d_out;
    const int M = Bc * Sc;  // 4096

    cudaFuncSetAttribute(gemm_h,
        cudaFuncAttributeMaxDynamicSharedMemorySize, 3*STG_B);
    size_t fsmem = (size_t)(128*QW + 64*QW + 64*QW + 8*16*PW) * sizeof(__half);
    cudaFuncSetAttribute(flash_h,
        cudaFuncAttributeMaxDynamicSharedMemorySize, (int)fsmem);

    rope_table_kernel<<<(Sc*(HDc/2) + 255)/256, 256>>>();

    __half *dxh, *dwq, *dwo;
    cudaGetSymbolAddress((void**)&dxh, g_x_h);
    cudaGetSymbolAddress((void**)&dwq, g_wqkv_t);
    cudaGetSymbolAddress((void**)&dwo, g_wout_t);

    {
        int n4 = Bc*Sc*Ec/4;
        cvt_h<<<(n4+255)/256, 256>>>((const float4*)x, (__half2*)dxh, n4);
    }
    transpose_cvt_h<<<dim3(3*Ac/32, Ec/32), 256>>>(wqkv, dwq, Ec, 3*Ac);
    transpose_cvt_h<<<dim3(Ec/32,   Ac/32), 256>>>(wout, dwo, Ac, Ec);

    // QKV GEMM + RoPE scatter
    gemm_h<<<dim3(3*Ac/128, M/128), 256, 3*STG_B>>>(nullptr, 3*Ac, Ec, 1);

    // Flash attention
    flash_h<<<dim3(Sc/128, Bc*Hc), 256, fsmem>>>();

    // Output projection
    gemm_h<<<dim3(Ec/128, M/128), 256, 3*STG_B>>>(out, Ec, Ac, 0);
}

// round 7
// speedup vs baseline: 8.0886x; 1.0017x over previous
#include <cuda_runtime.h>
#include <cuda_fp16.h>
#include <math.h>
#include <stdint.h>

#define Bc  2
#define Sc  2048
#define Ec  2048
#define Ac  2048
#define Hc  16
#define HDc 128

// Scratch (device globals), fp16 operands.
__device__ __half g_Q[Bc*Hc*Sc*HDc];
__device__ __half g_K[Bc*Hc*Sc*HDc];
__device__ __half g_V[Bc*Hc*Sc*HDc];
__device__ __half g_attn[Bc*Sc*Ac];          // attention out (fp16)
__device__ __half g_x_h[Bc*Sc*Ec];           // x fp16 [4096][2048]
__device__ __half g_wqkv_t[3*Ac*Ec];         // W_qkv^T fp16 [6144][2048]
__device__ __half g_wout_t[Ec*Ac];           // W_out^T fp16 [2048][2048]
__device__ float  g_cos[Sc*(HDc/2)];
__device__ float  g_sin[Sc*(HDc/2)];

// ---------------------------------------------------------------------------
__device__ __forceinline__ void mma_h(float* c, const unsigned* a, const unsigned* b) {
    asm volatile("mma.sync.aligned.m16n8k16.row.col.f32.f16.f16.f32 "
        "{%0,%1,%2,%3}, {%4,%5,%6,%7}, {%8,%9}, {%0,%1,%2,%3};"
        : "+f"(c[0]), "+f"(c[1]), "+f"(c[2]), "+f"(c[3])
        : "r"(a[0]), "r"(a[1]), "r"(a[2]), "r"(a[3]), "r"(b[0]), "r"(b[1]));
}
__device__ __forceinline__ void ldm_x4(unsigned& r0, unsigned& r1, unsigned& r2,
                                       unsigned& r3, unsigned addr) {
    asm volatile("ldmatrix.sync.aligned.m8n8.x4.shared.b16 {%0,%1,%2,%3}, [%4];"
        : "=r"(r0), "=r"(r1), "=r"(r2), "=r"(r3) : "r"(addr));
}
__device__ __forceinline__ void ldm_x4_t(unsigned& r0, unsigned& r1, unsigned& r2,
                                         unsigned& r3, unsigned addr) {
    asm volatile("ldmatrix.sync.aligned.m8n8.x4.trans.shared.b16 {%0,%1,%2,%3}, [%4];"
        : "=r"(r0), "=r"(r1), "=r"(r2), "=r"(r3) : "r"(addr));
}
__device__ __forceinline__ void cp16(void* smem_dst, const void* gsrc) {
    unsigned d = (unsigned)__cvta_generic_to_shared(smem_dst);
    asm volatile("cp.async.cg.shared.global [%0], [%1], 16;" :: "r"(d), "l"(gsrc));
}
__device__ __forceinline__ void cp_commit() { asm volatile("cp.async.commit_group;"); }
__device__ __forceinline__ unsigned smem_u32(const void* p) {
    return (unsigned)__cvta_generic_to_shared(p);
}

// ---------------------------------------------------------------------------
__global__ void rope_table_kernel() {
    int idx = blockIdx.x * blockDim.x + threadIdx.x;
    if (idx >= Sc * (HDc/2)) return;
    int pos = idx / (HDc/2);
    int j   = idx % (HDc/2);
    double inv = pow(10000.0, -((double)(2*j)) / (double)HDc);
    double a = (double)pos * inv;
    g_cos[idx] = (float)cos(a);
    g_sin[idx] = (float)sin(a);
}

__global__ void cvt_h(const float4* __restrict__ src, __half2* __restrict__ dst, int n4) {
    int i = blockIdx.x * blockDim.x + threadIdx.x;
    if (i < n4) {
        float4 v = src[i];
        dst[2*i]   = __floats2half2_rn(v.x, v.y);
        dst[2*i+1] = __floats2half2_rn(v.z, v.w);
    }
}

// Transpose + fp16 convert: src fp32 [R][C] -> dst fp16 [C][R]
__global__ __launch_bounds__(256) void transpose_cvt_h(
    const float* __restrict__ src, __half* __restrict__ dst, int R, int Ccols) {
    __shared__ __half tile[32][33];
    int c0 = blockIdx.x*32, r0 = blockIdx.y*32;
    int tx = threadIdx.x & 31, ty = threadIdx.x >> 5;
    #pragma unroll
    for (int i = 0; i < 4; i++)
        tile[ty + 8*i][tx] = __float2half(src[(size_t)(r0 + ty + 8*i)*Ccols + c0 + tx]);
    __syncthreads();
    #pragma unroll
    for (int i = 0; i < 4; i++)
        dst[(size_t)(c0 + ty + 8*i)*R + r0 + tx] = tile[tx][ty + 8*i];
}

// ---------------------------------------------------------------------------
// fp16 tensor-core GEMM: 128x128 tile, BK=32, 8 warps (2x4, warp tile 64x32),
// 3-stage cp.async, ldmatrix fragments. Both operands K-major fp16.
// mode 1: A=g_x_h, B=g_wqkv_t -> RoPE scatter to g_Q/g_K/g_V (fp16).
// mode 0: A=g_attn, B=g_wout_t -> fp32 C.
// ---------------------------------------------------------------------------
#define AW 40                         // padded row width (halves)
#define STG_H (2*128*AW)              // halves per stage (A+B)
#define STG_B (STG_H*2)               // bytes per stage

__global__ __launch_bounds__(256, 2) void gemm_h(
    float* __restrict__ C, int N, int K, int mode)
{
    extern __shared__ __half hs[];

    const __half* Ag = mode ? g_x_h : g_attn;
    const __half* Bg = mode ? g_wqkv_t : g_wout_t;

    int tid  = threadIdx.x;
    int warp = tid >> 5, lane = tid & 31;
    int lr = lane & 7, lq = lane >> 3;
    int g = lane >> 2, t4 = lane & 3;
    int wm = warp >> 2, wn = warp & 3;
    int m0 = blockIdx.y * 128, n0 = blockIdx.x * 128;
    unsigned sbase = smem_u32(hs);

    float acc[4][4][4];
    #pragma unroll
    for (int i = 0; i < 4; i++)
        #pragma unroll
        for (int j = 0; j < 4; j++)
            #pragma unroll
            for (int r = 0; r < 4; r++) acc[i][j][r] = 0.f;

    int T = K / 32;

    // stage loader: A tile 128x32, B tile 128x32 (both K-major)
    auto load_stage = [&](int s, int kt) {
        __half* As = hs + s*STG_H;
        __half* Bs = As + 128*AW;
        #pragma unroll
        for (int i = 0; i < 2; i++) {
            int c = tid + i*256;
            int row = c >> 2, kc = (c & 3) * 8;
            cp16(As + row*AW + kc, Ag + (size_t)(m0+row)*K + kt*32 + kc);
            cp16(Bs + row*AW + kc, Bg + (size_t)(n0+row)*K + kt*32 + kc);
        }
        cp_commit();
    };

    load_stage(0, 0);
    load_stage(1, 1);

    for (int it = 0; it < T; it++) {
        asm volatile("cp.async.wait_group 1;");
        __syncthreads();
        if (it + 2 < T) load_stage((it+2) % 3, it+2);
        else cp_commit();

        unsigned abase = sbase + (it % 3) * STG_B;
        unsigned bbase = abase + 128*AW*2;

        #pragma unroll
        for (int kk = 0; kk < 32; kk += 16) {
            unsigned a[4][4], b[4][2];
            #pragma unroll
            for (int mf = 0; mf < 4; mf++) {
                int row  = wm*64 + mf*16 + (lq & 1)*8 + lr;
                int kcol = kk + (lq >> 1)*8;
                ldm_x4(a[mf][0], a[mf][1], a[mf][2], a[mf][3],
                       abase + (row*AW + kcol)*2);
            }
            #pragma unroll
            for (int np = 0; np < 2; np++) {
                int row  = wn*32 + np*16 + (lq >> 1)*8 + lr;
                int kcol = kk + (lq & 1)*8;
                ldm_x4(b[np*2][0], b[np*2][1], b[np*2+1][0], b[np*2+1][1],
                       bbase + (row*AW + kcol)*2);
            }
            #pragma unroll
            for (int mf = 0; mf < 4; mf++)
                #pragma unroll
                for (int nf = 0; nf < 4; nf++)
                    mma_h(acc[mf][nf], a[mf], b[nf]);
        }
    }

    if (mode == 0) {
        #pragma unroll
        for (int mf = 0; mf < 4; mf++)
            #pragma unroll
            for (int nf = 0; nf < 4; nf++) {
                int row = m0 + wm*64 + mf*16 + g;
                int col = n0 + wn*32 + nf*8 + 2*t4;
                *(float2*)(C + (size_t)row*N + col) =
                    make_float2(acc[mf][nf][0], acc[mf][nf][1]);
                *(float2*)(C + (size_t)(row+8)*N + col) =
                    make_float2(acc[mf][nf][2], acc[mf][nf][3]);
            }
    } else {
        #pragma unroll
        for (int nf = 0; nf < 4; nf++) {
            int n   = n0 + wn*32 + nf*8 + 2*t4;
            int t   = n / 2048;
            int rem = n % 2048;
            int h   = rem >> 7;
            int d   = rem & 127;
            int j   = d >> 1;
            __half* dst = (t == 0) ? g_Q : (t == 1) ? g_K : g_V;
            #pragma unroll
            for (int mf = 0; mf < 4; mf++) {
                #pragma unroll
                for (int half = 0; half < 2; half++) {
                    int row = m0 + wm*64 + mf*16 + g + half*8;
                    int b = row >> 11, s = row & 2047;
                    float c0 = acc[mf][nf][half*2];
                    float c1 = acc[mf][nf][half*2 + 1];
                    __half2* p = (__half2*)(dst
                        + (((size_t)(b*Hc + h)*Sc + s) << 7) + d);
                    if (t == 2) *p = __floats2half2_rn(c0, c1);
                    else {
                        float cs = g_cos[s*64 + j], sn = g_sin[s*64 + j];
                        *p = __floats2half2_rn(c0*cs - c1*sn, c0*sn + c1*cs);
                    }
                }
            }
        }
    }
}

// ---------------------------------------------------------------------------
// fp16 flash attention. BM=128, BN=64, 256 threads (8 warps x 16 q-rows).
// ldmatrix everywhere; fp32 scores/softmax/O-accum; P stored fp16.
// ---------------------------------------------------------------------------
#define QW 136
#define PW 72

__global__ __launch_bounds__(256, 1) void flash_h() {
    extern __shared__ __half sh[];
    __half* Qs = sh;                   // [128][136]
    __half* Ks = Qs + 128*QW;          // [64][136]
    __half* Vs = Ks + 64*QW;           // [64][136]
    __half* Ps = Vs + 64*QW;           // 8 x [16][72]

    int tid  = threadIdx.x;
    int warp = tid >> 5, lane = tid & 31;
    int lr = lane & 7, lq = lane >> 3;
    int g = lane >> 2, t4 = lane & 3;
    int qb = blockIdx.x, bh = blockIdx.y;

    const __half* Qg = g_Q + (((size_t)bh*Sc + qb*128) << 7);
    const __half* Kg = g_K + ((size_t)bh*Sc << 7);
    const __half* Vg = g_V + ((size_t)bh*Sc << 7);

    unsigned qbase = smem_u32(Qs);
    unsigned kbase = smem_u32(Ks);
    unsigned vbase = smem_u32(Vs);
    unsigned pbase = smem_u32(Ps) + warp*16*PW*2;

    // Q: 128 rows x 128 halves = 2048 16B chunks
    #pragma unroll
    for (int i = 0; i < 8; i++) {
        int c = tid + i*256;
        int row = c >> 4, kc = (c & 15) * 8;
        cp16(Qs + row*QW + kc, Qg + row*128 + kc);
    }
    // K(0): 1024 chunks
    #pragma unroll
    for (int i = 0; i < 4; i++) {
        int c = tid + i*256;
        int row = c >> 4, kc = (c & 15) * 8;
        cp16(Ks + row*QW + kc, Kg + row*128 + kc);
    }
    cp_commit();

    float m_i[2] = {-INFINITY, -INFINITY}, l_i[2] = {0.f, 0.f};
    float o[16][4];
    #pragma unroll
    for (int nf = 0; nf < 16; nf++)
        #pragma unroll
        for (int r = 0; r < 4; r++) o[nf][r] = 0.f;

    const float scale = 0.08838834764831845f;
    int rbase = warp * 16;

    asm volatile("cp.async.wait_group 0;");
    __syncthreads();

    for (int kt = 0; kt < Sc/64; kt++) {
        // prefetch V(kt) under S-compute
        #pragma unroll
        for (int i = 0; i < 4; i++) {
            int c = tid + i*256;
            int row = c >> 4, kc = (c & 15) * 8;
            cp16(Vs + row*QW + kc, Vg + (size_t)kt*8192 + row*128 + kc);
        }
        cp_commit();

        // S = Q @ K^T  (8 k16-steps over d=128)
        float s[8][4];
        #pragma unroll
        for (int nf = 0; nf < 8; nf++)
            #pragma unroll
            for (int r = 0; r < 4; r++) s[nf][r] = 0.f;

        #pragma unroll
        for (int ks = 0; ks < 8; ks++) {
            int kd = ks*16;
            unsigned a[4], b[8][2];
            {
                int row  = rbase + (lq & 1)*8 + lr;
                int kcol = kd + (lq >> 1)*8;
                ldm_x4(a[0], a[1], a[2], a[3], qbase + (row*QW + kcol)*2);
            }
            #pragma unroll
            for (int np = 0; np < 4; np++) {
                int row  = np*16 + (lq >> 1)*8 + lr;
                int kcol = kd + (lq & 1)*8;
                ldm_x4(b[np*2][0], b[np*2][1], b[np*2+1][0], b[np*2+1][1],
                       kbase + (row*QW + kcol)*2);
            }
            #pragma unroll
            for (int nf = 0; nf < 8; nf++) mma_h(s[nf], a, b[nf]);
        }

        // online softmax (rows rbase+g, rbase+g+8)
        #pragma unroll
        for (int half = 0; half < 2; half++) {
            float mx = -INFINITY;
            #pragma unroll
            for (int nf = 0; nf < 8; nf++)
                mx = fmaxf(mx, fmaxf(s[nf][half*2], s[nf][half*2+1]));
            mx *= scale;
            mx = fmaxf(mx, __shfl_xor_sync(0xffffffffu, mx, 1));
            mx = fmaxf(mx, __shfl_xor_sync(0xffffffffu, mx, 2));
            float m_new = fmaxf(m_i[half], mx);
            float corr  = __expf(m_i[half] - m_new);
            float lsum  = 0.f;
            #pragma unroll
            for (int nf = 0; nf < 8; nf++) {
                float p0 = __expf(s[nf][half*2]   * scale - m_new);
                float p1 = __expf(s[nf][half*2+1] * scale - m_new);
                s[nf][half*2]   = p0;
                s[nf][half*2+1] = p1;
                lsum += p0 + p1;
            }
            lsum += __shfl_xor_sync(0xffffffffu, lsum, 1);
            lsum += __shfl_xor_sync(0xffffffffu, lsum, 2);
            l_i[half] = l_i[half] * corr + lsum;
            m_i[half] = m_new;
            #pragma unroll
            for (int nf = 0; nf < 16; nf++) {
                o[nf][half*2]   *= corr;
                o[nf][half*2+1] *= corr;
            }
        }

        // P -> smem (fp16)
        __half* Pw = Ps + warp*16*PW;
        #pragma unroll
        for (int nf = 0; nf < 8; nf++) {
            int col = nf*8 + 2*t4;
            *(__half2*)&Pw[g*PW + col]     = __floats2half2_rn(s[nf][0], s[nf][1]);
            *(__half2*)&Pw[(g+8)*PW + col] = __floats2half2_rn(s[nf][2], s[nf][3]);
        }

        asm volatile("cp.async.wait_group 0;");   // V(kt) landed
        __syncthreads();

        // prefetch K(kt+1) under O-compute
        if (kt + 1 < Sc/64) {
            #pragma unroll
            for (int i = 0; i < 4; i++) {
                int c = tid + i*256;
                int row = c >> 4, kc = (c & 15) * 8;
                cp16(Ks + row*QW + kc, Kg + (size_t)(kt+1)*8192 + row*128 + kc);
            }
        }
        cp_commit();

        // O += P @ V  (4 k16-steps over kv=64)
        #pragma unroll
        for (int ks = 0; ks < 4; ks++) {
            int kv = ks*16;
            unsigned a[4], b[16][2];
            {
                int row  = (lq & 1)*8 + lr;
                int kcol = kv + (lq >> 1)*8;
                ldm_x4(a[0], a[1], a[2], a[3], pbase + (row*PW + kcol)*2);
            }
            #pragma unroll
            for (int np = 0; np < 8; np++) {
                int row = kv + (lq & 1)*8 + lr;       // kv row
                int col = np*16 + (lq >> 1)*8;        // d col
                ldm_x4_t(b[np*2][0], b[np*2][1], b[np*2+1][0], b[np*2+1][1],
                         vbase + (row*QW + col)*2);
            }
            #pragma unroll
            for (int nf = 0; nf < 16; nf++) mma_h(o[nf], a, b[nf]);
        }

        asm volatile("cp.async.wait_group 0;");   // K(kt+1) landed
        __syncthreads();
    }

    // epilogue: normalize, write fp16 to g_attn [b, s, h*128+d]
    int b = bh / Hc, h = bh % Hc;
    float inv0 = 1.f / l_i[0], inv1 = 1.f / l_i[1];
    #pragma unroll
    for (int nf = 0; nf < 16; nf++) {
        int d = nf*8 + 2*t4;
        int r0 = qb*128 + rbase + g;
        __half2* p0 = (__half2*)(g_attn + (((size_t)(b*Sc + r0)) << 11) + h*128 + d);
        *p0 = __floats2half2_rn(o[nf][0]*inv0, o[nf][1]*inv0);
        __half2* p1 = (__half2*)(g_attn + (((size_t)(b*Sc + r0 + 8)) << 11) + h*128 + d);
        *p1 = __floats2half2_rn(o[nf][2]*inv1, o[nf][3]*inv1);
    }
}

// ---------------------------------------------------------------------------
extern "C" void kernel_launch(void* const* d_in, const int* in_sizes, int n_in,
                              void* d_out, int out_size) {
    const float *x = nullptr, *wqkv = nullptr, *wout = nullptr;
    for (int i = 0; i < n_in; i++) {
        int sz = in_sizes[i];
        if (sz == Bc*Sc*Ec)     x    = (const float*)d_in[i];
        else if (sz == Ec*3*Ac) wqkv = (const float*)d_in[i];
        else if (sz == Ac*Ec)   wout = (const float*)d_in[i];
    }
    float* out = (float*)d_out;
    const int M = Bc * Sc;  // 4096

    cudaFuncSetAttribute(gemm_h,
        cudaFuncAttributeMaxDynamicSharedMemorySize, 3*STG_B);
    size_t fsmem = (size_t)(128*QW + 64*QW + 64*QW + 8*16*PW) * sizeof(__half);
    cudaFuncSetAttribute(flash_h,
        cudaFuncAttributeMaxDynamicSharedMemorySize, (int)fsmem);

    rope_table_kernel<<<(Sc*(HDc/2) + 255)/256, 256>>>();

    __half *dxh, *dwq, *dwo;
    cudaGetSymbolAddress((void**)&dxh, g_x_h);
    cudaGetSymbolAddress((void**)&dwq, g_wqkv_t);
    cudaGetSymbolAddress((void**)&dwo, g_wout_t);

    {
        int n4 = Bc*Sc*Ec/4;
        cvt_h<<<(n4+255)/256, 256>>>((const float4*)x, (__half2*)dxh, n4);
    }
    transpose_cvt_h<<<dim3(3*Ac/32, Ec/32), 256>>>(wqkv, dwq, Ec, 3*Ac);
    transpose_cvt_h<<<dim3(Ec/32,   Ac/32), 256>>>(wout, dwo, Ac, Ec);

    // QKV GEMM + RoPE scatter
    gemm_h<<<dim3(3*Ac/128, M/128), 256, 3*STG_B>>>(nullptr, 3*Ac, Ec, 1);

    // Flash attention
    flash_h<<<dim3(Sc/128, Bc*Hc), 256, fsmem>>>();

    // Output projection
    gemm_h<<<dim3(Ec/128, M/128), 256, 3*STG_B>>>(out, Ec, Ac, 0);
}